// round 7
// baseline (speedup 1.0000x reference)
#include <cuda_runtime.h>

#define BB  16
#define SS  168
#define NN  200
#define HH  128
#define TT  24
#define NHH 4
#define DHH 32

#define EPITCH  172
#define E4      43
#define SCPITCH 172
#define SC4     43

// shared layout (floats)
#define OFF_ET  0
#define OFF_QR  22016              // 128*172
#define OFF_QB  (OFF_QR + 3072)
#define OFF_QT  (OFF_QB + 3072)    // 96*128 (qtilde / ce / gates 24*512)
#define OFF_SC  (OFF_QT + 12288)   // 96*172 scores/attn; later small bufs; weight stage for P1/P2
#define SMEM_FLOATS (OFF_SC + 16512)
#define SMEM_BYTES  (SMEM_FLOATS * 4)   // 227840

#define AGG_SMEM (NN * HH * 4)     // 102400

typedef unsigned long long ull;

__device__ __forceinline__ ull ffma2(ull a, ull b, ull c) {
    ull d;
    asm("fma.rn.f32x2 %0, %1, %2, %3;" : "=l"(d) : "l"(a), "l"(b), "l"(c));
    return d;
}
__device__ __forceinline__ ull dup2(float x) {
    ull d;
    asm("mov.b64 %0, {%1, %1};" : "=l"(d) : "r"(__float_as_uint(x)));
    return d;
}
__device__ __forceinline__ float2 unpk(ull a) {
    float2 f;
    asm("mov.b64 {%0, %1}, %2;" : "=f"(f.x), "=f"(f.y) : "l"(a));
    return f;
}

__device__ float g_WkT[HH * HH];
__device__ float g_agg[2][BB * NN * HH];
__device__ float g_aggWh[2][BB * NN * 4 * HH];

__global__ void k_prep(const float* __restrict__ Wk) {
    int idx = blockIdx.x * 256 + threadIdx.x;
    if (idx < HH * HH) {
        int j = idx / HH, hd = idx % HH;
        g_WkT[hd * HH + j] = Wk[j * HH + hd];
    }
}

// agg[l][b][n][hh] = sum_m adj[n][m] * h_l[b][m][hh]; one block per (l,b,c5): 40 rows
__global__ __launch_bounds__(512, 1)
void k_agg(const float* __restrict__ h0, const float* __restrict__ h1,
           const float* __restrict__ adj) {
    extern __shared__ float hS[];  // [200*128]
    int c5 = blockIdx.x / 32;
    int lb = blockIdx.x % 32;
    int l = lb >> 4, b = lb & 15;
    const float* hsrc = (l ? h1 : h0) + (size_t)b * NN * HH;
    for (int idx = threadIdx.x; idx < NN * HH; idx += 512) hS[idx] = hsrc[idx];
    __syncthreads();
    int hh = threadIdx.x & 127, g = threadIdx.x >> 7;  // g 0..3
    const float4* adj4 = (const float4*)adj;           // row pitch 50 float4
    int n0 = g * 50 + c5 * 10;
    float acc[10];
    #pragma unroll
    for (int k = 0; k < 10; k++) acc[k] = 0.f;
    for (int m4 = 0; m4 < 50; m4++) {
        float4 av[10];
        #pragma unroll
        for (int k = 0; k < 10; k++) av[k] = adj4[(n0 + k) * 50 + m4];
        #pragma unroll
        for (int u = 0; u < 4; u++) {
            float hv = hS[(m4 * 4 + u) * HH + hh];
            #pragma unroll
            for (int k = 0; k < 10; k++)
                acc[k] += ((const float*)&av[k])[u] * hv;
        }
    }
    #pragma unroll
    for (int k = 0; k < 10; k++)
        g_agg[l][((size_t)b * NN + n0 + k) * HH + hh] = acc[k];
}

// aggWh[l][b][n][c] = agg[l][b][n][:] @ Wh_l[:,c] + b_l[c]; one block per (l,b,ch): 50 rows
__global__ __launch_bounds__(512, 1)
void k_aggWh(const float* __restrict__ Wh0, const float* __restrict__ bb0,
             const float* __restrict__ Wh1, const float* __restrict__ bb1) {
    extern __shared__ float aggS[];  // [200*128]
    int ch = blockIdx.x >> 5;
    int lb = blockIdx.x & 31;
    int l = lb >> 4, b = lb & 15;
    const float* Wh   = l ? Wh1 : Wh0;
    const float* bias = l ? bb1 : bb0;
    const float* asrc = g_agg[l] + (size_t)b * NN * HH;
    for (int idx = threadIdx.x; idx < NN * HH; idx += 512) aggS[idx] = asrc[idx];
    __syncthreads();
    int c = threadIdx.x;
    float bsv = bias[c];
    const float4* a4 = (const float4*)aggS;  // row pitch 32 float4
    float* dst = g_aggWh[l] + (size_t)b * NN * 4 * HH;
    int n0 = ch * 50;
    float acc[50];
    #pragma unroll
    for (int k = 0; k < 50; k++) acc[k] = bsv;
    for (int i4 = 0; i4 < 32; i4++) {
        float w0 = Wh[(i4 * 4 + 0) * 512 + c];
        float w1 = Wh[(i4 * 4 + 1) * 512 + c];
        float w2 = Wh[(i4 * 4 + 2) * 512 + c];
        float w3 = Wh[(i4 * 4 + 3) * 512 + c];
        #pragma unroll
        for (int k = 0; k < 50; k++) {
            float4 a = a4[(n0 + k) * 32 + i4];
            acc[k] += a.x * w0 + a.y * w1 + a.z * w2 + a.w * w3;
        }
    }
    #pragma unroll
    for (int k = 0; k < 50; k++) dst[(n0 + k) * 512 + c] = acc[k];
}

__device__ __forceinline__ float sigf(float x) {
    return __fdividef(1.f, 1.f + __expf(fminf(-x, 80.f)));
}
__device__ __forceinline__ float tanhfast(float x) {
    float e = __expf(fminf(2.f * x, 80.f));
    return __fdividef(e - 1.f, e + 1.f);
}

// stage exactly 16384 floats (64KB) into smem, all 512 threads
__device__ __forceinline__ void stage16k(float* __restrict__ dst,
                                         const float* __restrict__ src, int tid) {
    const float4* s4 = (const float4*)src;
    float4* d4 = (float4*)dst;
    #pragma unroll
    for (int i = 0; i < 8; i++) d4[tid + 512 * i] = s4[tid + 512 * i];
}

__global__ __launch_bounds__(512, 1)
void k_mega(const float* __restrict__ enc,  const float* __restrict__ c0g,
            const float* __restrict__ h1g,  const float* __restrict__ c1g,
            const float* __restrict__ stepq,
            const float* __restrict__ Wq,   const float* __restrict__ bq,
            const float* __restrict__ Wv,   const float* __restrict__ bv,
            const float* __restrict__ Wo,   const float* __restrict__ bo,
            const float* __restrict__ ctxW, const float* __restrict__ ctxb,
            const float* __restrict__ Wx0,  const float* __restrict__ lng0, const float* __restrict__ lnb0,
            const float* __restrict__ Wx1,  const float* __restrict__ lng1, const float* __restrict__ lnb1,
            const float* __restrict__ outW, const float* __restrict__ outb,
            float* __restrict__ out_pred,   float* __restrict__ out_attn)
{
    extern __shared__ float sm[];
    float* eT   = sm + OFF_ET;   // [j*172 + s]; later weight stage area
    float* qr   = sm + OFF_QR;   // [t*128 + i]
    float* qb   = sm + OFF_QB;   // q proj; later ctx
    float* qt   = sm + OFF_QT;   // qtilde/ce [r*128+j]; gates [t*512+c]
    float* sc   = sm + OFF_SC;   // P1/P2 weight stage; scores/attn [r*172+s]
    float* obuf = sc;            // overlays after attn consumed
    float* comb = sc + 3072;
    float* lnxT = sc + 6144;     // transposed LN output [i*24 + t], 128*24
    float* x1b  = sc + 9216;
    float* x2b  = sc + 12288;

    const int tid = threadIdx.x;
    const int b = blockIdx.x / NN, n = blockIdx.x % NN;
    const int rowbase = (b * NN + n) * HH;

    // ---- P0: encoder tile transposed + query rows + stage Wq ----
    for (int idx = tid; idx < SS * HH; idx += 512) {
        int s = idx >> 7, j = idx & 127;
        eT[j * EPITCH + s] = enc[((size_t)(b * SS + s) * NN + n) * HH + j];
    }
    for (int idx = tid; idx < TT * HH; idx += 512) {
        int t = idx >> 7, i = idx & 127;
        qr[idx] = stepq[t * HH + i] + h1g[rowbase + i];
    }
    stage16k(sc, Wq, tid);
    __syncthreads();

    const int c128 = tid & 127, rh = tid >> 7;  // rh 0..3: 6 rows each

    // ---- P1: q = qr @ Wq + bq ----
    {
        float acc[6];
        float bqv = bq[c128];
        #pragma unroll
        for (int k = 0; k < 6; k++) acc[k] = bqv;
        const float4* qr4 = (const float4*)(qr + rh * 6 * HH);
        #pragma unroll 4
        for (int i4 = 0; i4 < 32; i4++) {
            float w0 = sc[(i4 * 4 + 0) * HH + c128];
            float w1 = sc[(i4 * 4 + 1) * HH + c128];
            float w2 = sc[(i4 * 4 + 2) * HH + c128];
            float w3 = sc[(i4 * 4 + 3) * HH + c128];
            #pragma unroll
            for (int k = 0; k < 6; k++) {
                float4 a = qr4[k * 32 + i4];
                acc[k] += a.x * w0 + a.y * w1 + a.z * w2 + a.w * w3;
            }
        }
        #pragma unroll
        for (int k = 0; k < 6; k++) qb[(rh * 6 + k) * HH + c128] = acc[k];
    }
    __syncthreads();

    // ---- P2: qtilde[t*4+h][j] = sum_d WkT[h*32+d][j] * q[t][h*32+d] ----
    stage16k(sc, g_WkT, tid);
    __syncthreads();
    {
        float acc[4][6];
        #pragma unroll
        for (int h = 0; h < 4; h++)
            #pragma unroll
            for (int k = 0; k < 6; k++) acc[h][k] = 0.f;
        const float4* qb4 = (const float4*)(qb + rh * 6 * HH);
        #pragma unroll 4
        for (int c4 = 0; c4 < 32; c4++) {  // c4 = h*8 + d4
            int h = c4 >> 3;
            float w0 = sc[(c4 * 4 + 0) * HH + c128];
            float w1 = sc[(c4 * 4 + 1) * HH + c128];
            float w2 = sc[(c4 * 4 + 2) * HH + c128];
            float w3 = sc[(c4 * 4 + 3) * HH + c128];
            #pragma unroll
            for (int k = 0; k < 6; k++) {
                float4 a = qb4[k * 32 + c4];
                acc[h][k] += a.x * w0 + a.y * w1 + a.z * w2 + a.w * w3;
            }
        }
        #pragma unroll
        for (int h = 0; h < 4; h++)
            #pragma unroll
            for (int k = 0; k < 6; k++)
                qt[((rh * 6 + k) * NHH + h) * HH + c128] = acc[h][k];
    }
    __syncthreads();

    // ---- P3: scores — f32x2 paired along s (ev float4 = 2 natural pairs) ----
    if (tid < 504) {
        int sb = tid % 42, rg = tid / 42;  // rg<12: 8 rows each; sb: 4 consecutive s
        ull acc2[8][2];
        #pragma unroll
        for (int k = 0; k < 8; k++) { acc2[k][0] = 0ULL; acc2[k][1] = 0ULL; }
        const float4* qt4 = (const float4*)qt + rg * 8 * 32;
        const ulonglong2* eT2 = (const ulonglong2*)eT;
        for (int j4 = 0; j4 < 32; j4++) {
            float4 qv[8];
            #pragma unroll
            for (int k = 0; k < 8; k++) qv[k] = qt4[k * 32 + j4];
            #pragma unroll
            for (int u = 0; u < 4; u++) {
                ulonglong2 ev = eT2[(j4 * 4 + u) * E4 + sb];
                #pragma unroll
                for (int k = 0; k < 8; k++) {
                    float q = (u == 0) ? qv[k].x : (u == 1) ? qv[k].y : (u == 2) ? qv[k].z : qv[k].w;
                    ull qd = dup2(q);
                    acc2[k][0] = ffma2(qd, ev.x, acc2[k][0]);
                    acc2[k][1] = ffma2(qd, ev.y, acc2[k][1]);
                }
            }
        }
        const float scale = 0.17677669529663687f;  // 1/sqrt(32)
        float4* sc4w = (float4*)sc;
        #pragma unroll
        for (int k = 0; k < 8; k++) {
            float2 a = unpk(acc2[k][0]);
            float2 b2 = unpk(acc2[k][1]);
            sc4w[(rg * 8 + k) * SC4 + sb] =
                make_float4(a.x * scale, a.y * scale, b2.x * scale, b2.y * scale);
        }
    }
    __syncthreads();

    // ---- P4: softmax over s; write attn ----
    {
        int warp = tid >> 5, lane = tid & 31;
        for (int r = warp; r < 96; r += 16) {
            float v[6];
            float mx = -1e30f;
            #pragma unroll
            for (int u = 0; u < 6; u++) {
                int s = lane + 32 * u;
                v[u] = (s < SS) ? sc[r * SCPITCH + s] : -1e30f;
                mx = fmaxf(mx, v[u]);
            }
            #pragma unroll
            for (int off = 16; off > 0; off >>= 1)
                mx = fmaxf(mx, __shfl_xor_sync(0xffffffffu, mx, off));
            float sum = 0.f;
            #pragma unroll
            for (int u = 0; u < 6; u++) {
                int s = lane + 32 * u;
                if (s < SS) { v[u] = __expf(v[u] - mx); sum += v[u]; }
            }
            #pragma unroll
            for (int off = 16; off > 0; off >>= 1)
                sum += __shfl_xor_sync(0xffffffffu, sum, off);
            float inv = __fdividef(1.f, sum);
            int t = r >> 2, h = r & 3;
            float* gout = out_attn + ((((size_t)b * TT + t) * NHH + h) * NN + n) * SS;
            #pragma unroll
            for (int u = 0; u < 6; u++) {
                int s = lane + 32 * u;
                if (s < SS) {
                    float a = v[u] * inv;
                    sc[r * SCPITCH + s] = a;
                    gout[s] = a;
                }
            }
        }
    }
    __syncthreads();

    // ---- P5: ce[r][j] = sum_s attn[r][s]*eT[j][s] — f32x2 along reduction s ----
    {
        int j0 = tid & 31, rg = tid >> 5;  // rg<16: 6 rows each
        ull acc2[4][6];
        #pragma unroll
        for (int u = 0; u < 4; u++)
            #pragma unroll
            for (int k = 0; k < 6; k++) acc2[u][k] = 0ULL;
        const ulonglong2* eT2 = (const ulonglong2*)eT;
        const ulonglong2* sc2 = (const ulonglong2*)sc;
        for (int s4 = 0; s4 < 42; s4++) {
            ulonglong2 av[6];
            #pragma unroll
            for (int k = 0; k < 6; k++) av[k] = sc2[(rg * 6 + k) * SC4 + s4];
            #pragma unroll
            for (int u = 0; u < 4; u++) {
                ulonglong2 ev = eT2[(j0 + 32 * u) * E4 + s4];
                #pragma unroll
                for (int k = 0; k < 6; k++) {
                    acc2[u][k] = ffma2(av[k].x, ev.x, acc2[u][k]);
                    acc2[u][k] = ffma2(av[k].y, ev.y, acc2[u][k]);
                }
            }
        }
        #pragma unroll
        for (int u = 0; u < 4; u++)
            #pragma unroll
            for (int k = 0; k < 6; k++) {
                float2 p = unpk(acc2[u][k]);
                qt[(rg * 6 + k) * HH + j0 + 32 * u] = p.x + p.y;
            }
    }
    __syncthreads();

    // ---- P6: ctx = ce @ Wv(head rows) + bv (into qb); Wv staged in eT ----
    stage16k(eT, Wv, tid);
    __syncthreads();
    {
        int h = c128 >> 5;
        float acc[6];
        float bvv = bv[c128];
        #pragma unroll
        for (int k = 0; k < 6; k++) acc[k] = bvv;
        const float4* ce4 = (const float4*)qt;
        #pragma unroll 4
        for (int j4 = 0; j4 < 32; j4++) {
            float w0 = eT[(j4 * 4 + 0) * HH + c128];
            float w1 = eT[(j4 * 4 + 1) * HH + c128];
            float w2 = eT[(j4 * 4 + 2) * HH + c128];
            float w3 = eT[(j4 * 4 + 3) * HH + c128];
            #pragma unroll
            for (int k = 0; k < 6; k++) {
                float4 a = ce4[((rh * 6 + k) * NHH + h) * 32 + j4];
                acc[k] += a.x * w0 + a.y * w1 + a.z * w2 + a.w * w3;
            }
        }
        #pragma unroll
        for (int k = 0; k < 6; k++) qb[(rh * 6 + k) * HH + c128] = acc[k];
    }
    __syncthreads();

    // ---- P7: o = ctx @ Wo + bo (into obuf); Wo staged in eT ----
    stage16k(eT, Wo, tid);
    __syncthreads();
    {
        float acc[6];
        float bov = bo[c128];
        #pragma unroll
        for (int k = 0; k < 6; k++) acc[k] = bov;
        const float4* cb4 = (const float4*)(qb + rh * 6 * HH);
        #pragma unroll 4
        for (int i4 = 0; i4 < 32; i4++) {
            float w0 = eT[(i4 * 4 + 0) * HH + c128];
            float w1 = eT[(i4 * 4 + 1) * HH + c128];
            float w2 = eT[(i4 * 4 + 2) * HH + c128];
            float w3 = eT[(i4 * 4 + 3) * HH + c128];
            #pragma unroll
            for (int k = 0; k < 6; k++) {
                float4 a = cb4[k * 32 + i4];
                acc[k] += a.x * w0 + a.y * w1 + a.z * w2 + a.w * w3;
            }
        }
        #pragma unroll
        for (int k = 0; k < 6; k++) obuf[(rh * 6 + k) * HH + c128] = acc[k];
    }
    __syncthreads();

    // ---- P8: combined = [qr | o] @ ctx_W + ctx_b; ctxW staged in 2 chunks ----
    {
        float acc[6];
        float cbv = ctxb[c128];
        #pragma unroll
        for (int k = 0; k < 6; k++) acc[k] = cbv;

        stage16k(eT, ctxW, tid);
        __syncthreads();
        const float4* qr4 = (const float4*)(qr + rh * 6 * HH);
        #pragma unroll 4
        for (int i4 = 0; i4 < 32; i4++) {
            float w0 = eT[(i4 * 4 + 0) * HH + c128];
            float w1 = eT[(i4 * 4 + 1) * HH + c128];
            float w2 = eT[(i4 * 4 + 2) * HH + c128];
            float w3 = eT[(i4 * 4 + 3) * HH + c128];
            #pragma unroll
            for (int k = 0; k < 6; k++) {
                float4 a = qr4[k * 32 + i4];
                acc[k] += a.x * w0 + a.y * w1 + a.z * w2 + a.w * w3;
            }
        }
        __syncthreads();
        stage16k(eT, ctxW + HH * HH, tid);
        __syncthreads();
        const float4* ob4 = (const float4*)(obuf + rh * 6 * HH);
        #pragma unroll 4
        for (int i4 = 0; i4 < 32; i4++) {
            float w0 = eT[(i4 * 4 + 0) * HH + c128];
            float w1 = eT[(i4 * 4 + 1) * HH + c128];
            float w2 = eT[(i4 * 4 + 2) * HH + c128];
            float w3 = eT[(i4 * 4 + 3) * HH + c128];
            #pragma unroll
            for (int k = 0; k < 6; k++) {
                float4 a = ob4[k * 32 + i4];
                acc[k] += a.x * w0 + a.y * w1 + a.z * w2 + a.w * w3;
            }
        }
        __syncthreads();
        #pragma unroll
        for (int k = 0; k < 6; k++) comb[(rh * 6 + k) * HH + c128] = acc[k];
    }
    __syncthreads();

    // ==== two GraphLSTM layers ====
    for (int layer = 0; layer < 2; layer++) {
        const float* src  = layer ? x1b : comb;
        const float* lg   = layer ? lng1 : lng0;
        const float* lb   = layer ? lnb1 : lnb0;
        const float* Wx   = layer ? Wx1 : Wx0;
        const float* cg   = layer ? c1g : c0g;
        const float* aggW = g_aggWh[layer] + (size_t)(b * NN + n) * 4 * HH;
        float* dst = layer ? x2b : x1b;

        // LN -> write TRANSPOSED lnxT[i*24 + t]
        {
            int warp = tid >> 5, lane = tid & 31;
            for (int t = warp; t < TT; t += 16) {
                float x[4];
                float s1 = 0.f;
                #pragma unroll
                for (int u = 0; u < 4; u++) { x[u] = src[t * HH + lane + 32 * u]; s1 += x[u]; }
                #pragma unroll
                for (int off = 16; off > 0; off >>= 1) s1 += __shfl_xor_sync(0xffffffffu, s1, off);
                float mean = s1 * (1.f / HH);
                float s2 = 0.f;
                #pragma unroll
                for (int u = 0; u < 4; u++) { float d = x[u] - mean; s2 += d * d; }
                #pragma unroll
                for (int off = 16; off > 0; off >>= 1) s2 += __shfl_xor_sync(0xffffffffu, s2, off);
                float inv = rsqrtf(s2 * (1.f / HH) + 1e-5f);
                #pragma unroll
                for (int u = 0; u < 4; u++) {
                    int i = lane + 32 * u;
                    lnxT[i * TT + t] = (x[u] - mean) * inv * lg[i] + lb[i];
                }
            }
        }
        __syncthreads();

        // gates = lnx @ Wx + aggWh — f32x2 paired along t (lnxT rows = natural pairs)
        {
            int c = tid;  // output column 0..511
            ull acc2[12];
            ull ainit = dup2(aggW[c]);
            #pragma unroll
            for (int k = 0; k < 12; k++) acc2[k] = ainit;
            for (int p = 0; p < 4; p++) {
                stage16k(eT, Wx + p * 32 * 512, tid);
                __syncthreads();
                #pragma unroll 4
                for (int i = 0; i < 32; i++) {  // global row = p*32 + i
                    ull wd = dup2(eT[i * 512 + c]);
                    const ulonglong2* lrow = (const ulonglong2*)(lnxT + (p * 32 + i) * TT);
                    #pragma unroll
                    for (int q = 0; q < 6; q++) {
                        ulonglong2 tp = lrow[q];  // t = 4q..4q+3 (2 pairs)
                        acc2[2 * q]     = ffma2(wd, tp.x, acc2[2 * q]);
                        acc2[2 * q + 1] = ffma2(wd, tp.y, acc2[2 * q + 1]);
                    }
                }
                __syncthreads();
            }
            #pragma unroll
            for (int k = 0; k < 12; k++) {
                float2 pp = unpk(acc2[k]);
                qt[(2 * k) * 512 + c]     = pp.x;
                qt[(2 * k + 1) * 512 + c] = pp.y;
            }
        }
        __syncthreads();

        // elementwise LSTM cell (+ residual on layer 1)
        for (int idx = tid; idx < TT * HH; idx += 512) {
            int t = idx >> 7, hh = idx & 127;
            float gi = qt[t * 512 + hh];
            float gf = qt[t * 512 + 128 + hh];
            float gg = qt[t * 512 + 256 + hh];
            float go = qt[t * 512 + 384 + hh];
            float cv = cg[rowbase + hh];
            float cn = sigf(gf) * cv + sigf(gi) * tanhfast(gg);
            float hv = sigf(go) * tanhfast(cn);
            dst[idx] = layer ? (hv + x1b[idx]) : hv;
        }
        __syncthreads();
    }

    // ---- preds = x2 @ out_W + out_b ----
    {
        int warp = tid >> 5, lane = tid & 31;
        float ob0 = outb[0];
        for (int t = warp; t < TT; t += 16) {
            float acc = 0.f;
            #pragma unroll
            for (int u = 0; u < 4; u++)
                acc += x2b[t * HH + lane + 32 * u] * outW[lane + 32 * u];
            #pragma unroll
            for (int off = 16; off > 0; off >>= 1)
                acc += __shfl_xor_sync(0xffffffffu, acc, off);
            if (lane == 0)
                out_pred[((size_t)b * TT + t) * NN + n] = acc + ob0;
        }
    }
}

extern "C" void kernel_launch(void* const* d_in, const int* in_sizes, int n_in,
                              void* d_out, int out_size) {
    const float* enc   = (const float*)d_in[0];
    const float* h0    = (const float*)d_in[1];
    const float* c0    = (const float*)d_in[2];
    const float* h1    = (const float*)d_in[3];
    const float* c1    = (const float*)d_in[4];
    const float* adj   = (const float*)d_in[5];
    const float* stepq = (const float*)d_in[6];
    const float* Wq    = (const float*)d_in[7];
    const float* bq    = (const float*)d_in[8];
    const float* Wk    = (const float*)d_in[9];
    // d_in[10] = bk: softmax-invariant, unused
    const float* Wv    = (const float*)d_in[11];
    const float* bv    = (const float*)d_in[12];
    const float* Wo    = (const float*)d_in[13];
    const float* bo    = (const float*)d_in[14];
    const float* ctxW  = (const float*)d_in[15];
    const float* ctxb  = (const float*)d_in[16];
    const float* Wx0   = (const float*)d_in[17];
    const float* Wh0   = (const float*)d_in[18];
    const float* b0    = (const float*)d_in[19];
    const float* lng0  = (const float*)d_in[20];
    const float* lnb0  = (const float*)d_in[21];
    const float* Wx1   = (const float*)d_in[22];
    const float* Wh1   = (const float*)d_in[23];
    const float* b1    = (const float*)d_in[24];
    const float* lng1  = (const float*)d_in[25];
    const float* lnb1  = (const float*)d_in[26];
    const float* outW  = (const float*)d_in[27];
    const float* outb  = (const float*)d_in[28];

    float* out      = (float*)d_out;
    float* out_pred = out;
    float* out_attn = out + (size_t)BB * TT * NN;

    cudaFuncSetAttribute(k_mega, cudaFuncAttributeMaxDynamicSharedMemorySize, SMEM_BYTES);
    cudaFuncSetAttribute(k_agg, cudaFuncAttributeMaxDynamicSharedMemorySize, AGG_SMEM);
    cudaFuncSetAttribute(k_aggWh, cudaFuncAttributeMaxDynamicSharedMemorySize, AGG_SMEM);

    k_prep<<<(HH * HH + 255) / 256, 256>>>(Wk);
    k_agg<<<5 * 2 * BB, 512, AGG_SMEM>>>(h0, h1, adj);
    k_aggWh<<<4 * 2 * BB, 512, AGG_SMEM>>>(Wh0, b0, Wh1, b1);
    k_mega<<<BB * NN, 512, SMEM_BYTES>>>(enc, c0, h1, c1, stepq,
                                         Wq, bq, Wv, bv, Wo, bo, ctxW, ctxb,
                                         Wx0, lng0, lnb0, Wx1, lng1, lnb1,
                                         outW, outb, out_pred, out_attn);
}

// round 8
// speedup vs baseline: 1.5718x; 1.5718x over previous
#include <cuda_runtime.h>

#define BB  16
#define SS  168
#define NN  200
#define HH  128
#define TT  24
#define NHH 4
#define DHH 32

#define EPITCH  172
#define E4      43
#define SCPITCH 172
#define SC4     43

// shared layout (floats)
#define OFF_ET  0
#define OFF_QR  22016              // 128*172
#define OFF_QB  (OFF_QR + 3072)
#define OFF_QT  (OFF_QB + 3072)    // 96*128 (qtilde / ce / gates 24*512)
#define OFF_SC  (OFF_QT + 12288)   // 96*172 scores/attn; later small bufs; weight stage for P1/P2
#define SMEM_FLOATS (OFF_SC + 16512)
#define SMEM_BYTES  (SMEM_FLOATS * 4)   // 227840

#define AGG_SMEM (NN * HH * 4)     // 102400

__device__ float g_WkT[HH * HH];
__device__ float g_agg[2][BB * NN * HH];
__device__ float g_aggWh[2][BB * NN * 4 * HH];

__global__ void k_prep(const float* __restrict__ Wk) {
    int idx = blockIdx.x * 256 + threadIdx.x;
    if (idx < HH * HH) {
        int j = idx / HH, hd = idx % HH;
        g_WkT[hd * HH + j] = Wk[j * HH + hd];
    }
}

// agg[l][b][n][hh] = sum_m adj[n][m] * h_l[b][m][hh]; one block per (l,b,c5): 40 rows
__global__ __launch_bounds__(512, 1)
void k_agg(const float* __restrict__ h0, const float* __restrict__ h1,
           const float* __restrict__ adj) {
    extern __shared__ float hS[];  // [200*128]
    int c5 = blockIdx.x / 32;
    int lb = blockIdx.x % 32;
    int l = lb >> 4, b = lb & 15;
    const float* hsrc = (l ? h1 : h0) + (size_t)b * NN * HH;
    for (int idx = threadIdx.x; idx < NN * HH; idx += 512) hS[idx] = hsrc[idx];
    __syncthreads();
    int hh = threadIdx.x & 127, g = threadIdx.x >> 7;  // g 0..3
    const float4* adj4 = (const float4*)adj;           // row pitch 50 float4
    int n0 = g * 50 + c5 * 10;
    float acc[10];
    #pragma unroll
    for (int k = 0; k < 10; k++) acc[k] = 0.f;
    for (int m4 = 0; m4 < 50; m4++) {
        float4 av[10];
        #pragma unroll
        for (int k = 0; k < 10; k++) av[k] = adj4[(n0 + k) * 50 + m4];
        #pragma unroll
        for (int u = 0; u < 4; u++) {
            float hv = hS[(m4 * 4 + u) * HH + hh];
            #pragma unroll
            for (int k = 0; k < 10; k++)
                acc[k] += ((const float*)&av[k])[u] * hv;
        }
    }
    #pragma unroll
    for (int k = 0; k < 10; k++)
        g_agg[l][((size_t)b * NN + n0 + k) * HH + hh] = acc[k];
}

// aggWh[l][b][n][c] = agg[l][b][n][:] @ Wh_l[:,c] + b_l[c]; one block per (l,b,ch): 50 rows
__global__ __launch_bounds__(512, 1)
void k_aggWh(const float* __restrict__ Wh0, const float* __restrict__ bb0,
             const float* __restrict__ Wh1, const float* __restrict__ bb1) {
    extern __shared__ float aggS[];  // [200*128]
    int ch = blockIdx.x >> 5;
    int lb = blockIdx.x & 31;
    int l = lb >> 4, b = lb & 15;
    const float* Wh   = l ? Wh1 : Wh0;
    const float* bias = l ? bb1 : bb0;
    const float* asrc = g_agg[l] + (size_t)b * NN * HH;
    for (int idx = threadIdx.x; idx < NN * HH; idx += 512) aggS[idx] = asrc[idx];
    __syncthreads();
    int c = threadIdx.x;
    float bsv = bias[c];
    const float4* a4 = (const float4*)aggS;  // row pitch 32 float4
    float* dst = g_aggWh[l] + (size_t)b * NN * 4 * HH;
    int n0 = ch * 50;
    float acc[50];
    #pragma unroll
    for (int k = 0; k < 50; k++) acc[k] = bsv;
    for (int i4 = 0; i4 < 32; i4++) {
        float w0 = Wh[(i4 * 4 + 0) * 512 + c];
        float w1 = Wh[(i4 * 4 + 1) * 512 + c];
        float w2 = Wh[(i4 * 4 + 2) * 512 + c];
        float w3 = Wh[(i4 * 4 + 3) * 512 + c];
        #pragma unroll
        for (int k = 0; k < 50; k++) {
            float4 a = a4[(n0 + k) * 32 + i4];
            acc[k] += a.x * w0 + a.y * w1 + a.z * w2 + a.w * w3;
        }
    }
    #pragma unroll
    for (int k = 0; k < 50; k++) dst[(n0 + k) * 512 + c] = acc[k];
}

__device__ __forceinline__ float sigf(float x) {
    return __fdividef(1.f, 1.f + __expf(fminf(-x, 80.f)));
}
__device__ __forceinline__ float tanhfast(float x) {
    float e = __expf(fminf(2.f * x, 80.f));
    return __fdividef(e - 1.f, e + 1.f);
}

// stage exactly 16384 floats (64KB) into smem, all 512 threads
__device__ __forceinline__ void stage16k(float* __restrict__ dst,
                                         const float* __restrict__ src, int tid) {
    const float4* s4 = (const float4*)src;
    float4* d4 = (float4*)dst;
    #pragma unroll
    for (int i = 0; i < 8; i++) d4[tid + 512 * i] = s4[tid + 512 * i];
}

__global__ __launch_bounds__(512, 1)
void k_mega(const float* __restrict__ enc,  const float* __restrict__ c0g,
            const float* __restrict__ h1g,  const float* __restrict__ c1g,
            const float* __restrict__ stepq,
            const float* __restrict__ Wq,   const float* __restrict__ bq,
            const float* __restrict__ Wv,   const float* __restrict__ bv,
            const float* __restrict__ Wo,   const float* __restrict__ bo,
            const float* __restrict__ ctxW, const float* __restrict__ ctxb,
            const float* __restrict__ Wx0,  const float* __restrict__ lng0, const float* __restrict__ lnb0,
            const float* __restrict__ Wx1,  const float* __restrict__ lng1, const float* __restrict__ lnb1,
            const float* __restrict__ outW, const float* __restrict__ outb,
            float* __restrict__ out_pred,   float* __restrict__ out_attn)
{
    extern __shared__ float sm[];
    float* eT   = sm + OFF_ET;   // [j*172 + s]; later weight stage area
    float* qr   = sm + OFF_QR;   // [t*128 + i]
    float* qb   = sm + OFF_QB;   // q proj; later ctx
    float* qt   = sm + OFF_QT;   // qtilde/ce [r*128+j]; gates [t*512+c]
    float* sc   = sm + OFF_SC;   // P1/P2 weight stage; scores/attn [r*172+s]
    float* obuf = sc;            // overlays after attn consumed
    float* comb = sc + 3072;
    float* lnx  = sc + 6144;
    float* x1b  = sc + 9216;
    float* x2b  = sc + 12288;

    const int tid = threadIdx.x;
    const int b = blockIdx.x / NN, n = blockIdx.x % NN;
    const int rowbase = (b * NN + n) * HH;

    // ---- P0: encoder tile transposed + query rows + stage Wq ----
    for (int idx = tid; idx < SS * HH; idx += 512) {
        int s = idx >> 7, j = idx & 127;
        eT[j * EPITCH + s] = enc[((size_t)(b * SS + s) * NN + n) * HH + j];
    }
    for (int idx = tid; idx < TT * HH; idx += 512) {
        int t = idx >> 7, i = idx & 127;
        qr[idx] = stepq[t * HH + i] + h1g[rowbase + i];
    }
    stage16k(sc, Wq, tid);
    __syncthreads();

    const int c128 = tid & 127, rh = tid >> 7;  // rh 0..3: 6 rows each

    // ---- P1: q = qr @ Wq + bq ----
    {
        float acc[6];
        float bqv = bq[c128];
        #pragma unroll
        for (int k = 0; k < 6; k++) acc[k] = bqv;
        const float4* qr4 = (const float4*)(qr + rh * 6 * HH);
        #pragma unroll 4
        for (int i4 = 0; i4 < 32; i4++) {
            float w0 = sc[(i4 * 4 + 0) * HH + c128];
            float w1 = sc[(i4 * 4 + 1) * HH + c128];
            float w2 = sc[(i4 * 4 + 2) * HH + c128];
            float w3 = sc[(i4 * 4 + 3) * HH + c128];
            #pragma unroll
            for (int k = 0; k < 6; k++) {
                float4 a = qr4[k * 32 + i4];
                acc[k] += a.x * w0 + a.y * w1 + a.z * w2 + a.w * w3;
            }
        }
        #pragma unroll
        for (int k = 0; k < 6; k++) qb[(rh * 6 + k) * HH + c128] = acc[k];
    }
    __syncthreads();

    // ---- P2: qtilde[t*4+h][j] = sum_d WkT[h*32+d][j] * q[t][h*32+d] ----
    stage16k(sc, g_WkT, tid);
    __syncthreads();
    {
        float acc[4][6];
        #pragma unroll
        for (int h = 0; h < 4; h++)
            #pragma unroll
            for (int k = 0; k < 6; k++) acc[h][k] = 0.f;
        const float4* qb4 = (const float4*)(qb + rh * 6 * HH);
        #pragma unroll 4
        for (int c4 = 0; c4 < 32; c4++) {  // c4 = h*8 + d4
            int h = c4 >> 3;
            float w0 = sc[(c4 * 4 + 0) * HH + c128];
            float w1 = sc[(c4 * 4 + 1) * HH + c128];
            float w2 = sc[(c4 * 4 + 2) * HH + c128];
            float w3 = sc[(c4 * 4 + 3) * HH + c128];
            #pragma unroll
            for (int k = 0; k < 6; k++) {
                float4 a = qb4[k * 32 + c4];
                acc[h][k] += a.x * w0 + a.y * w1 + a.z * w2 + a.w * w3;
            }
        }
        #pragma unroll
        for (int h = 0; h < 4; h++)
            #pragma unroll
            for (int k = 0; k < 6; k++)
                qt[((rh * 6 + k) * NHH + h) * HH + c128] = acc[h][k];
    }
    __syncthreads();

    // ---- P3: scores[r][sb*4..+3] — float4 on both operands ----
    if (tid < 504) {
        int sb = tid % 42, rg = tid / 42;  // rg<12: 8 rows each; sb: 4 consecutive s
        float acc[8][4];
        #pragma unroll
        for (int k = 0; k < 8; k++)
            #pragma unroll
            for (int m = 0; m < 4; m++) acc[k][m] = 0.f;
        const float4* qt4 = (const float4*)qt + rg * 8 * 32;
        const float4* eT4 = (const float4*)eT;
        for (int j4 = 0; j4 < 32; j4++) {
            float4 qv[8];
            #pragma unroll
            for (int k = 0; k < 8; k++) qv[k] = qt4[k * 32 + j4];
            #pragma unroll
            for (int u = 0; u < 4; u++) {
                float4 ev = eT4[(j4 * 4 + u) * E4 + sb];
                #pragma unroll
                for (int k = 0; k < 8; k++) {
                    float q = (u == 0) ? qv[k].x : (u == 1) ? qv[k].y : (u == 2) ? qv[k].z : qv[k].w;
                    acc[k][0] += q * ev.x;
                    acc[k][1] += q * ev.y;
                    acc[k][2] += q * ev.z;
                    acc[k][3] += q * ev.w;
                }
            }
        }
        const float scale = 0.17677669529663687f;  // 1/sqrt(32)
        float4* sc4w = (float4*)sc;
        #pragma unroll
        for (int k = 0; k < 8; k++)
            sc4w[(rg * 8 + k) * SC4 + sb] =
                make_float4(acc[k][0] * scale, acc[k][1] * scale, acc[k][2] * scale, acc[k][3] * scale);
    }
    __syncthreads();

    // ---- P4: softmax over s; write attn ----
    {
        int warp = tid >> 5, lane = tid & 31;
        for (int r = warp; r < 96; r += 16) {
            float v[6];
            float mx = -1e30f;
            #pragma unroll
            for (int u = 0; u < 6; u++) {
                int s = lane + 32 * u;
                v[u] = (s < SS) ? sc[r * SCPITCH + s] : -1e30f;
                mx = fmaxf(mx, v[u]);
            }
            #pragma unroll
            for (int off = 16; off > 0; off >>= 1)
                mx = fmaxf(mx, __shfl_xor_sync(0xffffffffu, mx, off));
            float sum = 0.f;
            #pragma unroll
            for (int u = 0; u < 6; u++) {
                int s = lane + 32 * u;
                if (s < SS) { v[u] = __expf(v[u] - mx); sum += v[u]; }
            }
            #pragma unroll
            for (int off = 16; off > 0; off >>= 1)
                sum += __shfl_xor_sync(0xffffffffu, sum, off);
            float inv = __fdividef(1.f, sum);
            int t = r >> 2, h = r & 3;
            float* gout = out_attn + ((((size_t)b * TT + t) * NHH + h) * NN + n) * SS;
            #pragma unroll
            for (int u = 0; u < 6; u++) {
                int s = lane + 32 * u;
                if (s < SS) {
                    float a = v[u] * inv;
                    sc[r * SCPITCH + s] = a;
                    gout[s] = a;
                }
            }
        }
    }
    __syncthreads();

    // ---- P5: ce[r][j] = sum_s attn[r][s]*eT[j][s]  (into qt) ----
    {
        int j0 = tid & 31, rg = tid >> 5;  // rg<16: 6 rows each
        float acc[4][6];
        #pragma unroll
        for (int u = 0; u < 4; u++)
            #pragma unroll
            for (int k = 0; k < 6; k++) acc[u][k] = 0.f;
        const float4* eT4 = (const float4*)eT;
        const float4* sc4 = (const float4*)sc;
        for (int s4 = 0; s4 < 42; s4++) {
            float4 av[6];
            #pragma unroll
            for (int k = 0; k < 6; k++) av[k] = sc4[(rg * 6 + k) * SC4 + s4];
            #pragma unroll
            for (int u = 0; u < 4; u++) {
                float4 ev = eT4[(j0 + 32 * u) * E4 + s4];
                #pragma unroll
                for (int k = 0; k < 6; k++)
                    acc[u][k] += av[k].x * ev.x + av[k].y * ev.y + av[k].z * ev.z + av[k].w * ev.w;
            }
        }
        #pragma unroll
        for (int u = 0; u < 4; u++)
            #pragma unroll
            for (int k = 0; k < 6; k++)
                qt[(rg * 6 + k) * HH + j0 + 32 * u] = acc[u][k];
    }
    __syncthreads();

    // ---- P6: ctx = ce @ Wv(head rows) + bv (into qb); Wv staged in eT ----
    stage16k(eT, Wv, tid);
    __syncthreads();
    {
        int h = c128 >> 5;
        float acc[6];
        float bvv = bv[c128];
        #pragma unroll
        for (int k = 0; k < 6; k++) acc[k] = bvv;
        const float4* ce4 = (const float4*)qt;
        #pragma unroll 4
        for (int j4 = 0; j4 < 32; j4++) {
            float w0 = eT[(j4 * 4 + 0) * HH + c128];
            float w1 = eT[(j4 * 4 + 1) * HH + c128];
            float w2 = eT[(j4 * 4 + 2) * HH + c128];
            float w3 = eT[(j4 * 4 + 3) * HH + c128];
            #pragma unroll
            for (int k = 0; k < 6; k++) {
                float4 a = ce4[((rh * 6 + k) * NHH + h) * 32 + j4];
                acc[k] += a.x * w0 + a.y * w1 + a.z * w2 + a.w * w3;
            }
        }
        #pragma unroll
        for (int k = 0; k < 6; k++) qb[(rh * 6 + k) * HH + c128] = acc[k];
    }
    __syncthreads();

    // ---- P7: o = ctx @ Wo + bo (into obuf); Wo staged in eT ----
    stage16k(eT, Wo, tid);
    __syncthreads();
    {
        float acc[6];
        float bov = bo[c128];
        #pragma unroll
        for (int k = 0; k < 6; k++) acc[k] = bov;
        const float4* cb4 = (const float4*)(qb + rh * 6 * HH);
        #pragma unroll 4
        for (int i4 = 0; i4 < 32; i4++) {
            float w0 = eT[(i4 * 4 + 0) * HH + c128];
            float w1 = eT[(i4 * 4 + 1) * HH + c128];
            float w2 = eT[(i4 * 4 + 2) * HH + c128];
            float w3 = eT[(i4 * 4 + 3) * HH + c128];
            #pragma unroll
            for (int k = 0; k < 6; k++) {
                float4 a = cb4[k * 32 + i4];
                acc[k] += a.x * w0 + a.y * w1 + a.z * w2 + a.w * w3;
            }
        }
        #pragma unroll
        for (int k = 0; k < 6; k++) obuf[(rh * 6 + k) * HH + c128] = acc[k];
    }
    __syncthreads();

    // ---- P8: combined = [qr | o] @ ctx_W + ctx_b; ctxW staged in 2 chunks ----
    {
        float acc[6];
        float cbv = ctxb[c128];
        #pragma unroll
        for (int k = 0; k < 6; k++) acc[k] = cbv;

        stage16k(eT, ctxW, tid);
        __syncthreads();
        const float4* qr4 = (const float4*)(qr + rh * 6 * HH);
        #pragma unroll 4
        for (int i4 = 0; i4 < 32; i4++) {
            float w0 = eT[(i4 * 4 + 0) * HH + c128];
            float w1 = eT[(i4 * 4 + 1) * HH + c128];
            float w2 = eT[(i4 * 4 + 2) * HH + c128];
            float w3 = eT[(i4 * 4 + 3) * HH + c128];
            #pragma unroll
            for (int k = 0; k < 6; k++) {
                float4 a = qr4[k * 32 + i4];
                acc[k] += a.x * w0 + a.y * w1 + a.z * w2 + a.w * w3;
            }
        }
        __syncthreads();
        stage16k(eT, ctxW + HH * HH, tid);
        __syncthreads();
        const float4* ob4 = (const float4*)(obuf + rh * 6 * HH);
        #pragma unroll 4
        for (int i4 = 0; i4 < 32; i4++) {
            float w0 = eT[(i4 * 4 + 0) * HH + c128];
            float w1 = eT[(i4 * 4 + 1) * HH + c128];
            float w2 = eT[(i4 * 4 + 2) * HH + c128];
            float w3 = eT[(i4 * 4 + 3) * HH + c128];
            #pragma unroll
            for (int k = 0; k < 6; k++) {
                float4 a = ob4[k * 32 + i4];
                acc[k] += a.x * w0 + a.y * w1 + a.z * w2 + a.w * w3;
            }
        }
        __syncthreads();
        #pragma unroll
        for (int k = 0; k < 6; k++) comb[(rh * 6 + k) * HH + c128] = acc[k];
    }
    __syncthreads();

    // ==== two GraphLSTM layers ====
    for (int layer = 0; layer < 2; layer++) {
        const float* src  = layer ? x1b : comb;
        const float* lg   = layer ? lng1 : lng0;
        const float* lb   = layer ? lnb1 : lnb0;
        const float* Wx   = layer ? Wx1 : Wx0;
        const float* cg   = layer ? c1g : c0g;
        const float* aggW = g_aggWh[layer] + (size_t)(b * NN + n) * 4 * HH;
        float* dst = layer ? x2b : x1b;

        // LN
        {
            int warp = tid >> 5, lane = tid & 31;
            for (int t = warp; t < TT; t += 16) {
                float x[4];
                float s1 = 0.f;
                #pragma unroll
                for (int u = 0; u < 4; u++) { x[u] = src[t * HH + lane + 32 * u]; s1 += x[u]; }
                #pragma unroll
                for (int off = 16; off > 0; off >>= 1) s1 += __shfl_xor_sync(0xffffffffu, s1, off);
                float mean = s1 * (1.f / HH);
                float s2 = 0.f;
                #pragma unroll
                for (int u = 0; u < 4; u++) { float d = x[u] - mean; s2 += d * d; }
                #pragma unroll
                for (int off = 16; off > 0; off >>= 1) s2 += __shfl_xor_sync(0xffffffffu, s2, off);
                float inv = rsqrtf(s2 * (1.f / HH) + 1e-5f);
                #pragma unroll
                for (int u = 0; u < 4; u++) {
                    int i = lane + 32 * u;
                    lnx[t * HH + i] = (x[u] - mean) * inv * lg[i] + lb[i];
                }
            }
        }
        __syncthreads();

        // gates = lnx @ Wx + aggWh  (into qt, pitch 512); Wx staged in 4 panels
        {
            int rh2 = tid >> 8, c = tid & 255;  // 12 rows each, cols c & c+256
            float acc0[12], acc1[12];
            float a0 = aggW[c], a1 = aggW[c + 256];
            #pragma unroll
            for (int k = 0; k < 12; k++) { acc0[k] = a0; acc1[k] = a1; }
            const float4* ln4 = (const float4*)(lnx + rh2 * 12 * HH);
            for (int p = 0; p < 4; p++) {
                stage16k(eT, Wx + p * 32 * 512, tid);
                __syncthreads();
                #pragma unroll 2
                for (int i4 = 0; i4 < 8; i4++) {  // global i = p*32 + i4*4 + u
                    float w00 = eT[(i4 * 4 + 0) * 512 + c];
                    float w01 = eT[(i4 * 4 + 1) * 512 + c];
                    float w02 = eT[(i4 * 4 + 2) * 512 + c];
                    float w03 = eT[(i4 * 4 + 3) * 512 + c];
                    float w10 = eT[(i4 * 4 + 0) * 512 + c + 256];
                    float w11 = eT[(i4 * 4 + 1) * 512 + c + 256];
                    float w12 = eT[(i4 * 4 + 2) * 512 + c + 256];
                    float w13 = eT[(i4 * 4 + 3) * 512 + c + 256];
                    #pragma unroll
                    for (int k = 0; k < 12; k++) {
                        float4 a = ln4[k * 32 + p * 8 + i4];
                        acc0[k] += a.x * w00 + a.y * w01 + a.z * w02 + a.w * w03;
                        acc1[k] += a.x * w10 + a.y * w11 + a.z * w12 + a.w * w13;
                    }
                }
                __syncthreads();
            }
            #pragma unroll
            for (int k = 0; k < 12; k++) {
                qt[(rh2 * 12 + k) * 512 + c]       = acc0[k];
                qt[(rh2 * 12 + k) * 512 + c + 256] = acc1[k];
            }
        }
        __syncthreads();

        // elementwise LSTM cell (+ residual on layer 1)
        for (int idx = tid; idx < TT * HH; idx += 512) {
            int t = idx >> 7, hh = idx & 127;
            float gi = qt[t * 512 + hh];
            float gf = qt[t * 512 + 128 + hh];
            float gg = qt[t * 512 + 256 + hh];
            float go = qt[t * 512 + 384 + hh];
            float cv = cg[rowbase + hh];
            float cn = sigf(gf) * cv + sigf(gi) * tanhfast(gg);
            float hv = sigf(go) * tanhfast(cn);
            dst[idx] = layer ? (hv + x1b[idx]) : hv;
        }
        __syncthreads();
    }

    // ---- preds = x2 @ out_W + out_b ----
    {
        int warp = tid >> 5, lane = tid & 31;
        float ob0 = outb[0];
        for (int t = warp; t < TT; t += 16) {
            float acc = 0.f;
            #pragma unroll
            for (int u = 0; u < 4; u++)
                acc += x2b[t * HH + lane + 32 * u] * outW[lane + 32 * u];
            #pragma unroll
            for (int off = 16; off > 0; off >>= 1)
                acc += __shfl_xor_sync(0xffffffffu, acc, off);
            if (lane == 0)
                out_pred[((size_t)b * TT + t) * NN + n] = acc + ob0;
        }
    }
}

extern "C" void kernel_launch(void* const* d_in, const int* in_sizes, int n_in,
                              void* d_out, int out_size) {
    const float* enc   = (const float*)d_in[0];
    const float* h0    = (const float*)d_in[1];
    const float* c0    = (const float*)d_in[2];
    const float* h1    = (const float*)d_in[3];
    const float* c1    = (const float*)d_in[4];
    const float* adj   = (const float*)d_in[5];
    const float* stepq = (const float*)d_in[6];
    const float* Wq    = (const float*)d_in[7];
    const float* bq    = (const float*)d_in[8];
    const float* Wk    = (const float*)d_in[9];
    // d_in[10] = bk: softmax-invariant, unused
    const float* Wv    = (const float*)d_in[11];
    const float* bv    = (const float*)d_in[12];
    const float* Wo    = (const float*)d_in[13];
    const float* bo    = (const float*)d_in[14];
    const float* ctxW  = (const float*)d_in[15];
    const float* ctxb  = (const float*)d_in[16];
    const float* Wx0   = (const float*)d_in[17];
    const float* Wh0   = (const float*)d_in[18];
    const float* b0    = (const float*)d_in[19];
    const float* lng0  = (const float*)d_in[20];
    const float* lnb0  = (const float*)d_in[21];
    const float* Wx1   = (const float*)d_in[22];
    const float* Wh1   = (const float*)d_in[23];
    const float* b1    = (const float*)d_in[24];
    const float* lng1  = (const float*)d_in[25];
    const float* lnb1  = (const float*)d_in[26];
    const float* outW  = (const float*)d_in[27];
    const float* outb  = (const float*)d_in[28];

    float* out      = (float*)d_out;
    float* out_pred = out;
    float* out_attn = out + (size_t)BB * TT * NN;

    cudaFuncSetAttribute(k_mega, cudaFuncAttributeMaxDynamicSharedMemorySize, SMEM_BYTES);
    cudaFuncSetAttribute(k_agg, cudaFuncAttributeMaxDynamicSharedMemorySize, AGG_SMEM);
    cudaFuncSetAttribute(k_aggWh, cudaFuncAttributeMaxDynamicSharedMemorySize, AGG_SMEM);

    k_prep<<<(HH * HH + 255) / 256, 256>>>(Wk);
    k_agg<<<5 * 2 * BB, 512, AGG_SMEM>>>(h0, h1, adj);
    k_aggWh<<<4 * 2 * BB, 512, AGG_SMEM>>>(Wh0, b0, Wh1, b1);
    k_mega<<<BB * NN, 512, SMEM_BYTES>>>(enc, c0, h1, c1, stepq,
                                         Wq, bq, Wv, bv, Wo, bo, ctxW, ctxb,
                                         Wx0, lng0, lnb0, Wx1, lng1, lnb1,
                                         outW, outb, out_pred, out_attn);
}

// round 9
// speedup vs baseline: 1.8478x; 1.1756x over previous
#include <cuda_runtime.h>

#define BB  16
#define SS  168
#define NN  200
#define HH  128
#define TT  24
#define NHH 4
#define DHH 32

#define EPITCH  172
#define E4      43
#define SCPITCH 172
#define SC4     43

// shared layout (floats)
#define OFF_ET  0
#define OFF_QR  22016              // 128*172 (region kept; mostly unused now)
#define OFF_QB  (OFF_QR + 3072)
#define OFF_QT  (OFF_QB + 3072)    // 96*128 (qtilde / ce / gates 24*512)
#define OFF_SC  (OFF_QT + 12288)   // 96*172 scores/attn; later small bufs
#define SMEM_FLOATS (OFF_SC + 16512)
#define SMEM_BYTES  (SMEM_FLOATS * 4)   // 227840

#define AGG_SMEM (NN * HH * 4)     // 102400

__device__ float g_W2[HH * 640];          // cols 0..511: WqkT per head; 512..639: ctxW top half
__device__ float g_bqk[512];              // bq @ Wk_head
__device__ float g_hfold[(size_t)BB * NN * 640];  // h1 @ W2 per (b,n)
__device__ float g_sfold[TT * 640];       // stepq @ W2 (+bqk on first 512 cols)
__device__ float g_agg[2][BB * NN * HH];
__device__ float g_aggWh[2][BB * NN * 4 * HH];

// W2[i, h*128+j] = sum_d Wq[i, h*32+d] * Wk[j, h*32+d];  W2[i, 512+c] = ctxW[i, c]
__global__ void k_w2(const float* __restrict__ Wq, const float* __restrict__ Wk,
                     const float* __restrict__ ctxW, const float* __restrict__ bq) {
    int idx = blockIdx.x * 256 + threadIdx.x;  // 0..81919
    int i = idx / 640, col = idx % 640;
    if (i < HH) {
        float acc;
        if (col < 512) {
            int h = col >> 7, j = col & 127;
            acc = 0.f;
            #pragma unroll 8
            for (int d = 0; d < 32; d++)
                acc += Wq[i * HH + h * 32 + d] * Wk[j * HH + h * 32 + d];
        } else {
            acc = ctxW[i * HH + (col - 512)];
        }
        g_W2[i * 640 + col] = acc;
    }
    if (idx < 512) {
        int h = idx >> 7, j = idx & 127;
        float a = 0.f;
        #pragma unroll 8
        for (int d = 0; d < 32; d++)
            a += bq[h * 32 + d] * Wk[j * HH + h * 32 + d];
        g_bqk[idx] = a;
    }
}

// fold rows: rows 0..3199 = h1 -> g_hfold; rows 3200..3223 = stepq -> g_sfold (+bqk)
__global__ __launch_bounds__(640, 1)
void k_fold(const float* __restrict__ h1, const float* __restrict__ stepq) {
    __shared__ float aS[8 * HH];
    int r0 = blockIdx.x * 8;
    bool isq = (r0 >= BB * NN);
    const float* src = isq ? (stepq + (r0 - BB * NN) * HH) : (h1 + (size_t)r0 * HH);
    for (int idx = threadIdx.x; idx < 8 * HH; idx += 640) aS[idx] = src[idx];
    __syncthreads();
    int c = threadIdx.x;  // 0..639
    float acc[8];
    float binit = (isq && c < 512) ? g_bqk[c] : 0.f;
    #pragma unroll
    for (int k = 0; k < 8; k++) acc[k] = binit;
    #pragma unroll 4
    for (int i = 0; i < HH; i++) {
        float w = g_W2[i * 640 + c];
        #pragma unroll
        for (int k = 0; k < 8; k++) acc[k] += aS[k * HH + i] * w;
    }
    float* dst = isq ? (g_sfold + (r0 - BB * NN) * 640) : (g_hfold + (size_t)r0 * 640);
    #pragma unroll
    for (int k = 0; k < 8; k++) dst[k * 640 + c] = acc[k];
}

// agg[l][b][n][hh] = sum_m adj[n][m] * h_l[b][m][hh]; one block per (l,b,c5): 40 rows
__global__ __launch_bounds__(512, 1)
void k_agg(const float* __restrict__ h0, const float* __restrict__ h1,
           const float* __restrict__ adj) {
    extern __shared__ float hS[];  // [200*128]
    int c5 = blockIdx.x / 32;
    int lb = blockIdx.x % 32;
    int l = lb >> 4, b = lb & 15;
    const float* hsrc = (l ? h1 : h0) + (size_t)b * NN * HH;
    for (int idx = threadIdx.x; idx < NN * HH; idx += 512) hS[idx] = hsrc[idx];
    __syncthreads();
    int hh = threadIdx.x & 127, g = threadIdx.x >> 7;  // g 0..3
    const float4* adj4 = (const float4*)adj;           // row pitch 50 float4
    int n0 = g * 50 + c5 * 10;
    float acc[10];
    #pragma unroll
    for (int k = 0; k < 10; k++) acc[k] = 0.f;
    for (int m4 = 0; m4 < 50; m4++) {
        float4 av[10];
        #pragma unroll
        for (int k = 0; k < 10; k++) av[k] = adj4[(n0 + k) * 50 + m4];
        #pragma unroll
        for (int u = 0; u < 4; u++) {
            float hv = hS[(m4 * 4 + u) * HH + hh];
            #pragma unroll
            for (int k = 0; k < 10; k++)
                acc[k] += ((const float*)&av[k])[u] * hv;
        }
    }
    #pragma unroll
    for (int k = 0; k < 10; k++)
        g_agg[l][((size_t)b * NN + n0 + k) * HH + hh] = acc[k];
}

// aggWh[l][b][n][c] = agg[l][b][n][:] @ Wh_l[:,c] + b_l[c]; one block per (l,b,ch): 50 rows
__global__ __launch_bounds__(512, 1)
void k_aggWh(const float* __restrict__ Wh0, const float* __restrict__ bb0,
             const float* __restrict__ Wh1, const float* __restrict__ bb1) {
    extern __shared__ float aggS[];  // [200*128]
    int ch = blockIdx.x >> 5;
    int lb = blockIdx.x & 31;
    int l = lb >> 4, b = lb & 15;
    const float* Wh   = l ? Wh1 : Wh0;
    const float* bias = l ? bb1 : bb0;
    const float* asrc = g_agg[l] + (size_t)b * NN * HH;
    for (int idx = threadIdx.x; idx < NN * HH; idx += 512) aggS[idx] = asrc[idx];
    __syncthreads();
    int c = threadIdx.x;
    float bsv = bias[c];
    const float4* a4 = (const float4*)aggS;  // row pitch 32 float4
    float* dst = g_aggWh[l] + (size_t)b * NN * 4 * HH;
    int n0 = ch * 50;
    float acc[50];
    #pragma unroll
    for (int k = 0; k < 50; k++) acc[k] = bsv;
    for (int i4 = 0; i4 < 32; i4++) {
        float w0 = Wh[(i4 * 4 + 0) * 512 + c];
        float w1 = Wh[(i4 * 4 + 1) * 512 + c];
        float w2 = Wh[(i4 * 4 + 2) * 512 + c];
        float w3 = Wh[(i4 * 4 + 3) * 512 + c];
        #pragma unroll
        for (int k = 0; k < 50; k++) {
            float4 a = a4[(n0 + k) * 32 + i4];
            acc[k] += a.x * w0 + a.y * w1 + a.z * w2 + a.w * w3;
        }
    }
    #pragma unroll
    for (int k = 0; k < 50; k++) dst[(n0 + k) * 512 + c] = acc[k];
}

__device__ __forceinline__ float sigf(float x) {
    return __fdividef(1.f, 1.f + __expf(fminf(-x, 80.f)));
}
__device__ __forceinline__ float tanhfast(float x) {
    float e = __expf(fminf(2.f * x, 80.f));
    return __fdividef(e - 1.f, e + 1.f);
}

// stage exactly 16384 floats (64KB) into smem, all 512 threads
__device__ __forceinline__ void stage16k(float* __restrict__ dst,
                                         const float* __restrict__ src, int tid) {
    const float4* s4 = (const float4*)src;
    float4* d4 = (float4*)dst;
    #pragma unroll
    for (int i = 0; i < 8; i++) d4[tid + 512 * i] = s4[tid + 512 * i];
}

__global__ __launch_bounds__(512, 1)
void k_mega(const float* __restrict__ enc,  const float* __restrict__ c0g,
            const float* __restrict__ c1g,
            const float* __restrict__ Wv,   const float* __restrict__ bv,
            const float* __restrict__ Wo,   const float* __restrict__ bo,
            const float* __restrict__ ctxW, const float* __restrict__ ctxb,
            const float* __restrict__ Wx0,  const float* __restrict__ lng0, const float* __restrict__ lnb0,
            const float* __restrict__ Wx1,  const float* __restrict__ lng1, const float* __restrict__ lnb1,
            const float* __restrict__ outW, const float* __restrict__ outb,
            float* __restrict__ out_pred,   float* __restrict__ out_attn)
{
    extern __shared__ float sm[];
    float* eT   = sm + OFF_ET;   // [j*172 + s]; later weight stage area
    float* qb   = sm + OFF_QB;   // ctx buffer
    float* qt   = sm + OFF_QT;   // qtilde/ce [r*128+j]; gates [t*512+c]
    float* sc   = sm + OFF_SC;   // scores/attn [r*172+s]
    float* obuf = sc;            // overlays after attn consumed
    float* comb = sc + 3072;
    float* lnx  = sc + 6144;
    float* x1b  = sc + 9216;
    float* x2b  = sc + 12288;

    const int tid = threadIdx.x;
    const int b = blockIdx.x / NN, n = blockIdx.x % NN;
    const int bn = b * NN + n;
    const int rowbase = bn * HH;

    // ---- P0: encoder tile transposed + qtilde from folds ----
    for (int idx = tid; idx < SS * HH; idx += 512) {
        int s = idx >> 7, j = idx & 127;
        eT[j * EPITCH + s] = enc[((size_t)(b * SS + s) * NN + n) * HH + j];
    }
    {
        const float4* sf4 = (const float4*)g_sfold;                       // pitch 160 f4/t
        const float4* hf4 = (const float4*)(g_hfold + (size_t)bn * 640);  // first 128 f4
        float4* qt4w = (float4*)qt;
        for (int i4 = tid; i4 < TT * 128; i4 += 512) {
            int t = i4 >> 7, u4 = i4 & 127;
            float4 sa = sf4[t * 160 + u4];
            float4 hb = hf4[u4];
            qt4w[i4] = make_float4(sa.x + hb.x, sa.y + hb.y, sa.z + hb.z, sa.w + hb.w);
        }
    }
    __syncthreads();

    const int c128 = tid & 127, rh = tid >> 7;  // rh 0..3: 6 rows each

    // ---- P3: scores[r][sb*4..+3] — float4 on both operands ----
    if (tid < 504) {
        int sb = tid % 42, rg = tid / 42;  // rg<12: 8 rows each; sb: 4 consecutive s
        float acc[8][4];
        #pragma unroll
        for (int k = 0; k < 8; k++)
            #pragma unroll
            for (int m = 0; m < 4; m++) acc[k][m] = 0.f;
        const float4* qt4 = (const float4*)qt + rg * 8 * 32;
        const float4* eT4 = (const float4*)eT;
        for (int j4 = 0; j4 < 32; j4++) {
            float4 qv[8];
            #pragma unroll
            for (int k = 0; k < 8; k++) qv[k] = qt4[k * 32 + j4];
            #pragma unroll
            for (int u = 0; u < 4; u++) {
                float4 ev = eT4[(j4 * 4 + u) * E4 + sb];
                #pragma unroll
                for (int k = 0; k < 8; k++) {
                    float q = (u == 0) ? qv[k].x : (u == 1) ? qv[k].y : (u == 2) ? qv[k].z : qv[k].w;
                    acc[k][0] += q * ev.x;
                    acc[k][1] += q * ev.y;
                    acc[k][2] += q * ev.z;
                    acc[k][3] += q * ev.w;
                }
            }
        }
        const float scale = 0.17677669529663687f;  // 1/sqrt(32)
        float4* sc4w = (float4*)sc;
        #pragma unroll
        for (int k = 0; k < 8; k++)
            sc4w[(rg * 8 + k) * SC4 + sb] =
                make_float4(acc[k][0] * scale, acc[k][1] * scale, acc[k][2] * scale, acc[k][3] * scale);
    }
    __syncthreads();

    // ---- P4: softmax over s; write attn ----
    {
        int warp = tid >> 5, lane = tid & 31;
        for (int r = warp; r < 96; r += 16) {
            float v[6];
            float mx = -1e30f;
            #pragma unroll
            for (int u = 0; u < 6; u++) {
                int s = lane + 32 * u;
                v[u] = (s < SS) ? sc[r * SCPITCH + s] : -1e30f;
                mx = fmaxf(mx, v[u]);
            }
            #pragma unroll
            for (int off = 16; off > 0; off >>= 1)
                mx = fmaxf(mx, __shfl_xor_sync(0xffffffffu, mx, off));
            float sum = 0.f;
            #pragma unroll
            for (int u = 0; u < 6; u++) {
                int s = lane + 32 * u;
                if (s < SS) { v[u] = __expf(v[u] - mx); sum += v[u]; }
            }
            #pragma unroll
            for (int off = 16; off > 0; off >>= 1)
                sum += __shfl_xor_sync(0xffffffffu, sum, off);
            float inv = __fdividef(1.f, sum);
            int t = r >> 2, h = r & 3;
            float* gout = out_attn + ((((size_t)b * TT + t) * NHH + h) * NN + n) * SS;
            #pragma unroll
            for (int u = 0; u < 6; u++) {
                int s = lane + 32 * u;
                if (s < SS) {
                    float a = v[u] * inv;
                    sc[r * SCPITCH + s] = a;
                    gout[s] = a;
                }
            }
        }
    }
    __syncthreads();

    // ---- P5: ce[r][j] = sum_s attn[r][s]*eT[j][s]  (into qt) ----
    {
        int j0 = tid & 31, rg = tid >> 5;  // rg<16: 6 rows each
        float acc[4][6];
        #pragma unroll
        for (int u = 0; u < 4; u++)
            #pragma unroll
            for (int k = 0; k < 6; k++) acc[u][k] = 0.f;
        const float4* eT4 = (const float4*)eT;
        const float4* sc4 = (const float4*)sc;
        for (int s4 = 0; s4 < 42; s4++) {
            float4 av[6];
            #pragma unroll
            for (int k = 0; k < 6; k++) av[k] = sc4[(rg * 6 + k) * SC4 + s4];
            #pragma unroll
            for (int u = 0; u < 4; u++) {
                float4 ev = eT4[(j0 + 32 * u) * E4 + s4];
                #pragma unroll
                for (int k = 0; k < 6; k++)
                    acc[u][k] += av[k].x * ev.x + av[k].y * ev.y + av[k].z * ev.z + av[k].w * ev.w;
            }
        }
        #pragma unroll
        for (int u = 0; u < 4; u++)
            #pragma unroll
            for (int k = 0; k < 6; k++)
                qt[(rg * 6 + k) * HH + j0 + 32 * u] = acc[u][k];
    }
    __syncthreads();

    // ---- P6: ctx = ce @ Wv(head rows) + bv (into qb); Wv staged in eT ----
    stage16k(eT, Wv, tid);
    __syncthreads();
    {
        int h = c128 >> 5;
        float acc[6];
        float bvv = bv[c128];
        #pragma unroll
        for (int k = 0; k < 6; k++) acc[k] = bvv;
        const float4* ce4 = (const float4*)qt;
        #pragma unroll 4
        for (int j4 = 0; j4 < 32; j4++) {
            float w0 = eT[(j4 * 4 + 0) * HH + c128];
            float w1 = eT[(j4 * 4 + 1) * HH + c128];
            float w2 = eT[(j4 * 4 + 2) * HH + c128];
            float w3 = eT[(j4 * 4 + 3) * HH + c128];
            #pragma unroll
            for (int k = 0; k < 6; k++) {
                float4 a = ce4[((rh * 6 + k) * NHH + h) * 32 + j4];
                acc[k] += a.x * w0 + a.y * w1 + a.z * w2 + a.w * w3;
            }
        }
        #pragma unroll
        for (int k = 0; k < 6; k++) qb[(rh * 6 + k) * HH + c128] = acc[k];
    }
    __syncthreads();

    // ---- P7: o = ctx @ Wo + bo (into obuf); Wo staged in eT ----
    stage16k(eT, Wo, tid);
    __syncthreads();
    {
        float acc[6];
        float bov = bo[c128];
        #pragma unroll
        for (int k = 0; k < 6; k++) acc[k] = bov;
        const float4* cb4 = (const float4*)(qb + rh * 6 * HH);
        #pragma unroll 4
        for (int i4 = 0; i4 < 32; i4++) {
            float w0 = eT[(i4 * 4 + 0) * HH + c128];
            float w1 = eT[(i4 * 4 + 1) * HH + c128];
            float w2 = eT[(i4 * 4 + 2) * HH + c128];
            float w3 = eT[(i4 * 4 + 3) * HH + c128];
            #pragma unroll
            for (int k = 0; k < 6; k++) {
                float4 a = cb4[k * 32 + i4];
                acc[k] += a.x * w0 + a.y * w1 + a.z * w2 + a.w * w3;
            }
        }
        #pragma unroll
        for (int k = 0; k < 6; k++) obuf[(rh * 6 + k) * HH + c128] = acc[k];
    }
    __syncthreads();

    // ---- P8: combined = (query@ctxW1 via folds) + o @ ctxW2 + ctx_b ----
    {
        float acc[6];
        const float* hfo = g_hfold + (size_t)bn * 640 + 512;
        float cbv = ctxb[c128] + hfo[c128];
        #pragma unroll
        for (int k = 0; k < 6; k++)
            acc[k] = cbv + g_sfold[(rh * 6 + k) * 640 + 512 + c128];

        stage16k(eT, ctxW + HH * HH, tid);
        __syncthreads();
        const float4* ob4 = (const float4*)(obuf + rh * 6 * HH);
        #pragma unroll 4
        for (int i4 = 0; i4 < 32; i4++) {
            float w0 = eT[(i4 * 4 + 0) * HH + c128];
            float w1 = eT[(i4 * 4 + 1) * HH + c128];
            float w2 = eT[(i4 * 4 + 2) * HH + c128];
            float w3 = eT[(i4 * 4 + 3) * HH + c128];
            #pragma unroll
            for (int k = 0; k < 6; k++) {
                float4 a = ob4[k * 32 + i4];
                acc[k] += a.x * w0 + a.y * w1 + a.z * w2 + a.w * w3;
            }
        }
        __syncthreads();
        #pragma unroll
        for (int k = 0; k < 6; k++) comb[(rh * 6 + k) * HH + c128] = acc[k];
    }
    __syncthreads();

    // ==== two GraphLSTM layers ====
    for (int layer = 0; layer < 2; layer++) {
        const float* src  = layer ? x1b : comb;
        const float* lg   = layer ? lng1 : lng0;
        const float* lb   = layer ? lnb1 : lnb0;
        const float* Wx   = layer ? Wx1 : Wx0;
        const float* cg   = layer ? c1g : c0g;
        const float* aggW = g_aggWh[layer] + (size_t)bn * 4 * HH;
        float* dst = layer ? x2b : x1b;

        // LN
        {
            int warp = tid >> 5, lane = tid & 31;
            for (int t = warp; t < TT; t += 16) {
                float x[4];
                float s1 = 0.f;
                #pragma unroll
                for (int u = 0; u < 4; u++) { x[u] = src[t * HH + lane + 32 * u]; s1 += x[u]; }
                #pragma unroll
                for (int off = 16; off > 0; off >>= 1) s1 += __shfl_xor_sync(0xffffffffu, s1, off);
                float mean = s1 * (1.f / HH);
                float s2 = 0.f;
                #pragma unroll
                for (int u = 0; u < 4; u++) { float d = x[u] - mean; s2 += d * d; }
                #pragma unroll
                for (int off = 16; off > 0; off >>= 1) s2 += __shfl_xor_sync(0xffffffffu, s2, off);
                float inv = rsqrtf(s2 * (1.f / HH) + 1e-5f);
                #pragma unroll
                for (int u = 0; u < 4; u++) {
                    int i = lane + 32 * u;
                    lnx[t * HH + i] = (x[u] - mean) * inv * lg[i] + lb[i];
                }
            }
        }
        __syncthreads();

        // gates = lnx @ Wx + aggWh  (into qt, pitch 512); Wx staged in 4 panels
        {
            int rh2 = tid >> 8, c = tid & 255;  // 12 rows each, cols c & c+256
            float acc0[12], acc1[12];
            float a0 = aggW[c], a1 = aggW[c + 256];
            #pragma unroll
            for (int k = 0; k < 12; k++) { acc0[k] = a0; acc1[k] = a1; }
            const float4* ln4 = (const float4*)(lnx + rh2 * 12 * HH);
            for (int p = 0; p < 4; p++) {
                stage16k(eT, Wx + p * 32 * 512, tid);
                __syncthreads();
                #pragma unroll 2
                for (int i4 = 0; i4 < 8; i4++) {  // global i = p*32 + i4*4 + u
                    float w00 = eT[(i4 * 4 + 0) * 512 + c];
                    float w01 = eT[(i4 * 4 + 1) * 512 + c];
                    float w02 = eT[(i4 * 4 + 2) * 512 + c];
                    float w03 = eT[(i4 * 4 + 3) * 512 + c];
                    float w10 = eT[(i4 * 4 + 0) * 512 + c + 256];
                    float w11 = eT[(i4 * 4 + 1) * 512 + c + 256];
                    float w12 = eT[(i4 * 4 + 2) * 512 + c + 256];
                    float w13 = eT[(i4 * 4 + 3) * 512 + c + 256];
                    #pragma unroll
                    for (int k = 0; k < 12; k++) {
                        float4 a = ln4[k * 32 + p * 8 + i4];
                        acc0[k] += a.x * w00 + a.y * w01 + a.z * w02 + a.w * w03;
                        acc1[k] += a.x * w10 + a.y * w11 + a.z * w12 + a.w * w13;
                    }
                }
                __syncthreads();
            }
            #pragma unroll
            for (int k = 0; k < 12; k++) {
                qt[(rh2 * 12 + k) * 512 + c]       = acc0[k];
                qt[(rh2 * 12 + k) * 512 + c + 256] = acc1[k];
            }
        }
        __syncthreads();

        // elementwise LSTM cell (+ residual on layer 1)
        for (int idx = tid; idx < TT * HH; idx += 512) {
            int t = idx >> 7, hh = idx & 127;
            float gi = qt[t * 512 + hh];
            float gf = qt[t * 512 + 128 + hh];
            float gg = qt[t * 512 + 256 + hh];
            float go = qt[t * 512 + 384 + hh];
            float cv = cg[rowbase + hh];
            float cn = sigf(gf) * cv + sigf(gi) * tanhfast(gg);
            float hv = sigf(go) * tanhfast(cn);
            dst[idx] = layer ? (hv + x1b[idx]) : hv;
        }
        __syncthreads();
    }

    // ---- preds = x2 @ out_W + out_b ----
    {
        int warp = tid >> 5, lane = tid & 31;
        float ob0 = outb[0];
        for (int t = warp; t < TT; t += 16) {
            float acc = 0.f;
            #pragma unroll
            for (int u = 0; u < 4; u++)
                acc += x2b[t * HH + lane + 32 * u] * outW[lane + 32 * u];
            #pragma unroll
            for (int off = 16; off > 0; off >>= 1)
                acc += __shfl_xor_sync(0xffffffffu, acc, off);
            if (lane == 0)
                out_pred[((size_t)b * TT + t) * NN + n] = acc + ob0;
        }
    }
}

extern "C" void kernel_launch(void* const* d_in, const int* in_sizes, int n_in,
                              void* d_out, int out_size) {
    const float* enc   = (const float*)d_in[0];
    const float* h0    = (const float*)d_in[1];
    const float* c0    = (const float*)d_in[2];
    const float* h1    = (const float*)d_in[3];
    const float* c1    = (const float*)d_in[4];
    const float* adj   = (const float*)d_in[5];
    const float* stepq = (const float*)d_in[6];
    const float* Wq    = (const float*)d_in[7];
    const float* bq    = (const float*)d_in[8];
    const float* Wk    = (const float*)d_in[9];
    // d_in[10] = bk: softmax-invariant, unused
    const float* Wv    = (const float*)d_in[11];
    const float* bv    = (const float*)d_in[12];
    const float* Wo    = (const float*)d_in[13];
    const float* bo    = (const float*)d_in[14];
    const float* ctxW  = (const float*)d_in[15];
    const float* ctxb  = (const float*)d_in[16];
    const float* Wx0   = (const float*)d_in[17];
    const float* Wh0   = (const float*)d_in[18];
    const float* b0    = (const float*)d_in[19];
    const float* lng0  = (const float*)d_in[20];
    const float* lnb0  = (const float*)d_in[21];
    const float* Wx1   = (const float*)d_in[22];
    const float* Wh1   = (const float*)d_in[23];
    const float* b1    = (const float*)d_in[24];
    const float* lng1  = (const float*)d_in[25];
    const float* lnb1  = (const float*)d_in[26];
    const float* outW  = (const float*)d_in[27];
    const float* outb  = (const float*)d_in[28];

    float* out      = (float*)d_out;
    float* out_pred = out;
    float* out_attn = out + (size_t)BB * TT * NN;

    cudaFuncSetAttribute(k_mega, cudaFuncAttributeMaxDynamicSharedMemorySize, SMEM_BYTES);
    cudaFuncSetAttribute(k_agg, cudaFuncAttributeMaxDynamicSharedMemorySize, AGG_SMEM);
    cudaFuncSetAttribute(k_aggWh, cudaFuncAttributeMaxDynamicSharedMemorySize, AGG_SMEM);

    k_w2<<<320, 256>>>(Wq, Wk, ctxW, bq);
    k_fold<<<(BB * NN + TT) / 8, 640>>>(h1, stepq);
    k_agg<<<5 * 2 * BB, 512, AGG_SMEM>>>(h0, h1, adj);
    k_aggWh<<<4 * 2 * BB, 512, AGG_SMEM>>>(Wh0, b0, Wh1, b1);
    k_mega<<<BB * NN, 512, SMEM_BYTES>>>(enc, c0, c1,
                                         Wv, bv, Wo, bo, ctxW, ctxb,
                                         Wx0, lng0, lnb0, Wx1, lng1, lnb1,
                                         outW, outb, out_pred, out_attn);
}

// round 11
// speedup vs baseline: 2.4016x; 1.2997x over previous
#include <cuda_runtime.h>
#include <cuda_bf16.h>
#include <cstdint>

#define BB  16
#define SS  168
#define NN  200
#define HH  128
#define TT  24
#define NHH 4
#define DHH 32
#define NROWS (BB * NN * TT)   // 76800

#define EPITCH  172
#define E4      43
#define SCPITCH 172
#define SC4     43

// k_attn shared layout (floats)
#define OFF_ET  0
#define OFF_QB  (22016 + 3072)
#define OFF_QT  (OFF_QB + 3072)
#define OFF_SC  (OFF_QT + 12288)
#define SMEM_FLOATS (OFF_SC + 16512)
#define SMEM_BYTES  (SMEM_FLOATS * 4)

#define AGG_SMEM (NN * HH * 4)

// k_gates smem layout (unsigned units, pitch 68)
#define GA_PITCH 68
#define G_AH  0
#define G_AL  (G_AH + 64 * GA_PITCH)
#define G_BH  (G_AL + 64 * GA_PITCH)
#define G_BL  (G_BH + 128 * GA_PITCH)
#define G_DS  (G_BL + 128 * GA_PITCH)            // float[64*33]
#define G_SMEM_BYTES ((G_DS + 64 * 33) * 4)      // 112896

// ---------------- device scratch ----------------
__device__ float g_W2[HH * 640];
__device__ float g_bqk[512];
__device__ float g_hfold[(size_t)BB * NN * 640];
__device__ float g_sfold[TT * 640];
__device__ float g_agg[2][BB * NN * HH];
__device__ float g_aggWh[2][BB * NN * 4 * HH];   // PERMUTED cols: p = hh*4 + gate
__device__ float g_comb[(size_t)NROWS * HH];
__device__ float g_x1[(size_t)NROWS * HH];
__device__ float g_x2[(size_t)NROWS * HH];
__device__ unsigned g_lnx_hi[(size_t)NROWS * 64];   // bf16x2 packed rows (low = even k)
__device__ unsigned g_lnx_lo[(size_t)NROWS * 64];
__device__ __nv_bfloat16 g_WxT_hi[2][512 * 128];    // [p][i], p = hh*4+gate
__device__ __nv_bfloat16 g_WxT_lo[2][512 * 128];

__device__ __forceinline__ float sigf(float x) {
    return __fdividef(1.f, 1.f + __expf(fminf(-x, 80.f)));
}
__device__ __forceinline__ float tanhfast(float x) {
    float e = __expf(fminf(2.f * x, 80.f));
    return __fdividef(e - 1.f, e + 1.f);
}
__device__ __forceinline__ unsigned pack_bf(float lo, float hi) {
    unsigned r;
    asm("cvt.rn.bf16x2.f32 %0, %1, %2;" : "=r"(r) : "f"(hi), "f"(lo));
    return r;
}
// HMMA m16n8k16 bf16 -> fp32 (family-portable, compiles at compute_103)
__device__ __forceinline__ void mma16816(float* c, unsigned a0, unsigned a1,
                                         unsigned a2, unsigned a3,
                                         unsigned b0, unsigned b1) {
    asm volatile(
        "mma.sync.aligned.m16n8k16.row.col.f32.bf16.bf16.f32 "
        "{%0,%1,%2,%3}, {%4,%5,%6,%7}, {%8,%9}, {%0,%1,%2,%3};"
        : "+f"(c[0]), "+f"(c[1]), "+f"(c[2]), "+f"(c[3])
        : "r"(a0), "r"(a1), "r"(a2), "r"(a3), "r"(b0), "r"(b1));
}

// ---------------- prep kernels ----------------
__global__ void k_w2(const float* __restrict__ Wq, const float* __restrict__ Wk,
                     const float* __restrict__ ctxW, const float* __restrict__ bq) {
    int idx = blockIdx.x * 256 + threadIdx.x;
    int i = idx / 640, col = idx % 640;
    if (i < HH) {
        float acc;
        if (col < 512) {
            int h = col >> 7, j = col & 127;
            acc = 0.f;
            #pragma unroll 8
            for (int d = 0; d < 32; d++)
                acc += Wq[i * HH + h * 32 + d] * Wk[j * HH + h * 32 + d];
        } else {
            acc = ctxW[i * HH + (col - 512)];
        }
        g_W2[i * 640 + col] = acc;
    }
    if (idx < 512) {
        int h = idx >> 7, j = idx & 127;
        float a = 0.f;
        #pragma unroll 8
        for (int d = 0; d < 32; d++)
            a += bq[h * 32 + d] * Wk[j * HH + h * 32 + d];
        g_bqk[idx] = a;
    }
}

// split-bf16 of PERMUTED WxT: p = hh*4+gate; WxT[p][i] = Wx[i][gate*128+hh]
__global__ void k_wprep(const float* __restrict__ Wx0, const float* __restrict__ Wx1) {
    int idx = blockIdx.x * 256 + threadIdx.x;
    if (idx >= 2 * 512 * 128) return;
    int l = idx / (512 * 128);
    int rem = idx % (512 * 128);
    int p = rem / 128, i = rem % 128;
    const float* Wx = l ? Wx1 : Wx0;
    float v = Wx[i * 512 + (p & 3) * 128 + (p >> 2)];
    __nv_bfloat16 hi = __float2bfloat16(v);
    float lo = v - __bfloat162float(hi);
    g_WxT_hi[l][p * 128 + i] = hi;
    g_WxT_lo[l][p * 128 + i] = __float2bfloat16(lo);
}

__global__ __launch_bounds__(640, 1)
void k_fold(const float* __restrict__ h1, const float* __restrict__ stepq) {
    __shared__ float aS[8 * HH];
    int r0 = blockIdx.x * 8;
    bool isq = (r0 >= BB * NN);
    const float* src = isq ? (stepq + (r0 - BB * NN) * HH) : (h1 + (size_t)r0 * HH);
    for (int idx = threadIdx.x; idx < 8 * HH; idx += 640) aS[idx] = src[idx];
    __syncthreads();
    int c = threadIdx.x;
    float acc[8];
    float binit = (isq && c < 512) ? g_bqk[c] : 0.f;
    #pragma unroll
    for (int k = 0; k < 8; k++) acc[k] = binit;
    #pragma unroll 4
    for (int i = 0; i < HH; i++) {
        float w = g_W2[i * 640 + c];
        #pragma unroll
        for (int k = 0; k < 8; k++) acc[k] += aS[k * HH + i] * w;
    }
    float* dst = isq ? (g_sfold + (r0 - BB * NN) * 640) : (g_hfold + (size_t)r0 * 640);
    #pragma unroll
    for (int k = 0; k < 8; k++) dst[k * 640 + c] = acc[k];
}

__global__ __launch_bounds__(512, 1)
void k_agg(const float* __restrict__ h0, const float* __restrict__ h1,
           const float* __restrict__ adj) {
    extern __shared__ float hS[];
    int c5 = blockIdx.x / 32;
    int lb = blockIdx.x % 32;
    int l = lb >> 4, b = lb & 15;
    const float* hsrc = (l ? h1 : h0) + (size_t)b * NN * HH;
    for (int idx = threadIdx.x; idx < NN * HH; idx += 512) hS[idx] = hsrc[idx];
    __syncthreads();
    int hh = threadIdx.x & 127, g = threadIdx.x >> 7;
    const float4* adj4 = (const float4*)adj;
    int n0 = g * 50 + c5 * 10;
    float acc[10];
    #pragma unroll
    for (int k = 0; k < 10; k++) acc[k] = 0.f;
    for (int m4 = 0; m4 < 50; m4++) {
        float4 av[10];
        #pragma unroll
        for (int k = 0; k < 10; k++) av[k] = adj4[(n0 + k) * 50 + m4];
        #pragma unroll
        for (int u = 0; u < 4; u++) {
            float hv = hS[(m4 * 4 + u) * HH + hh];
            #pragma unroll
            for (int k = 0; k < 10; k++)
                acc[k] += ((const float*)&av[k])[u] * hv;
        }
    }
    #pragma unroll
    for (int k = 0; k < 10; k++)
        g_agg[l][((size_t)b * NN + n0 + k) * HH + hh] = acc[k];
}

// aggWh with PERMUTED column store: p = (c&127)*4 + (c>>7)
__global__ __launch_bounds__(512, 1)
void k_aggWh(const float* __restrict__ Wh0, const float* __restrict__ bb0,
             const float* __restrict__ Wh1, const float* __restrict__ bb1) {
    extern __shared__ float aggS[];
    int ch = blockIdx.x >> 5;
    int lb = blockIdx.x & 31;
    int l = lb >> 4, b = lb & 15;
    const float* Wh   = l ? Wh1 : Wh0;
    const float* bias = l ? bb1 : bb0;
    const float* asrc = g_agg[l] + (size_t)b * NN * HH;
    for (int idx = threadIdx.x; idx < NN * HH; idx += 512) aggS[idx] = asrc[idx];
    __syncthreads();
    int c = threadIdx.x;
    int perm = (c & 127) * 4 + (c >> 7);
    float bsv = bias[c];
    const float4* a4 = (const float4*)aggS;
    float* dst = g_aggWh[l] + (size_t)b * NN * 4 * HH;
    int n0 = ch * 50;
    float acc[50];
    #pragma unroll
    for (int k = 0; k < 50; k++) acc[k] = bsv;
    for (int i4 = 0; i4 < 32; i4++) {
        float w0 = Wh[(i4 * 4 + 0) * 512 + c];
        float w1 = Wh[(i4 * 4 + 1) * 512 + c];
        float w2 = Wh[(i4 * 4 + 2) * 512 + c];
        float w3 = Wh[(i4 * 4 + 3) * 512 + c];
        #pragma unroll
        for (int k = 0; k < 50; k++) {
            float4 a = a4[(n0 + k) * 32 + i4];
            acc[k] += a.x * w0 + a.y * w1 + a.z * w2 + a.w * w3;
        }
    }
    #pragma unroll
    for (int k = 0; k < 50; k++) dst[(n0 + k) * 512 + perm] = acc[k];
}

__device__ __forceinline__ void stage16k(float* __restrict__ dst,
                                         const float* __restrict__ src, int tid) {
    const float4* s4 = (const float4*)src;
    float4* d4 = (float4*)dst;
    #pragma unroll
    for (int i = 0; i < 8; i++) d4[tid + 512 * i] = s4[tid + 512 * i];
}

// ---------------- attention megakernel (through comb) ----------------
__global__ __launch_bounds__(512, 1)
void k_attn(const float* __restrict__ enc,
            const float* __restrict__ Wv,   const float* __restrict__ bv,
            const float* __restrict__ Wo,   const float* __restrict__ bo,
            const float* __restrict__ ctxW, const float* __restrict__ ctxb,
            float* __restrict__ out_attn)
{
    extern __shared__ float sm[];
    float* eT   = sm + OFF_ET;
    float* qb   = sm + OFF_QB;
    float* qt   = sm + OFF_QT;
    float* sc   = sm + OFF_SC;
    float* obuf = sc;

    const int tid = threadIdx.x;
    const int b = blockIdx.x / NN, n = blockIdx.x % NN;
    const int bn = b * NN + n;

    for (int idx = tid; idx < SS * HH; idx += 512) {
        int s = idx >> 7, j = idx & 127;
        eT[j * EPITCH + s] = enc[((size_t)(b * SS + s) * NN + n) * HH + j];
    }
    {
        const float4* sf4 = (const float4*)g_sfold;
        const float4* hf4 = (const float4*)(g_hfold + (size_t)bn * 640);
        float4* qt4w = (float4*)qt;
        for (int i4 = tid; i4 < TT * 128; i4 += 512) {
            int t = i4 >> 7, u4 = i4 & 127;
            float4 sa = sf4[t * 160 + u4];
            float4 hb = hf4[u4];
            qt4w[i4] = make_float4(sa.x + hb.x, sa.y + hb.y, sa.z + hb.z, sa.w + hb.w);
        }
    }
    __syncthreads();

    const int c128 = tid & 127, rh = tid >> 7;

    // scores
    if (tid < 504) {
        int sb = tid % 42, rg = tid / 42;
        float acc[8][4];
        #pragma unroll
        for (int k = 0; k < 8; k++)
            #pragma unroll
            for (int m = 0; m < 4; m++) acc[k][m] = 0.f;
        const float4* qt4 = (const float4*)qt + rg * 8 * 32;
        const float4* eT4 = (const float4*)eT;
        for (int j4 = 0; j4 < 32; j4++) {
            float4 qv[8];
            #pragma unroll
            for (int k = 0; k < 8; k++) qv[k] = qt4[k * 32 + j4];
            #pragma unroll
            for (int u = 0; u < 4; u++) {
                float4 ev = eT4[(j4 * 4 + u) * E4 + sb];
                #pragma unroll
                for (int k = 0; k < 8; k++) {
                    float q = (u == 0) ? qv[k].x : (u == 1) ? qv[k].y : (u == 2) ? qv[k].z : qv[k].w;
                    acc[k][0] += q * ev.x;
                    acc[k][1] += q * ev.y;
                    acc[k][2] += q * ev.z;
                    acc[k][3] += q * ev.w;
                }
            }
        }
        const float scale = 0.17677669529663687f;
        float4* sc4w = (float4*)sc;
        #pragma unroll
        for (int k = 0; k < 8; k++)
            sc4w[(rg * 8 + k) * SC4 + sb] =
                make_float4(acc[k][0] * scale, acc[k][1] * scale, acc[k][2] * scale, acc[k][3] * scale);
    }
    __syncthreads();

    // softmax + attn out
    {
        int warp = tid >> 5, lane = tid & 31;
        for (int r = warp; r < 96; r += 16) {
            float v[6];
            float mx = -1e30f;
            #pragma unroll
            for (int u = 0; u < 6; u++) {
                int s = lane + 32 * u;
                v[u] = (s < SS) ? sc[r * SCPITCH + s] : -1e30f;
                mx = fmaxf(mx, v[u]);
            }
            #pragma unroll
            for (int off = 16; off > 0; off >>= 1)
                mx = fmaxf(mx, __shfl_xor_sync(0xffffffffu, mx, off));
            float sum = 0.f;
            #pragma unroll
            for (int u = 0; u < 6; u++) {
                int s = lane + 32 * u;
                if (s < SS) { v[u] = __expf(v[u] - mx); sum += v[u]; }
            }
            #pragma unroll
            for (int off = 16; off > 0; off >>= 1)
                sum += __shfl_xor_sync(0xffffffffu, sum, off);
            float inv = __fdividef(1.f, sum);
            int t = r >> 2, h = r & 3;
            float* gout = out_attn + ((((size_t)b * TT + t) * NHH + h) * NN + n) * SS;
            #pragma unroll
            for (int u = 0; u < 6; u++) {
                int s = lane + 32 * u;
                if (s < SS) {
                    float a = v[u] * inv;
                    sc[r * SCPITCH + s] = a;
                    gout[s] = a;
                }
            }
        }
    }
    __syncthreads();

    // ce
    {
        int j0 = tid & 31, rg = tid >> 5;
        float acc[4][6];
        #pragma unroll
        for (int u = 0; u < 4; u++)
            #pragma unroll
            for (int k = 0; k < 6; k++) acc[u][k] = 0.f;
        const float4* eT4 = (const float4*)eT;
        const float4* sc4 = (const float4*)sc;
        for (int s4 = 0; s4 < 42; s4++) {
            float4 av[6];
            #pragma unroll
            for (int k = 0; k < 6; k++) av[k] = sc4[(rg * 6 + k) * SC4 + s4];
            #pragma unroll
            for (int u = 0; u < 4; u++) {
                float4 ev = eT4[(j0 + 32 * u) * E4 + s4];
                #pragma unroll
                for (int k = 0; k < 6; k++)
                    acc[u][k] += av[k].x * ev.x + av[k].y * ev.y + av[k].z * ev.z + av[k].w * ev.w;
            }
        }
        #pragma unroll
        for (int u = 0; u < 4; u++)
            #pragma unroll
            for (int k = 0; k < 6; k++)
                qt[(rg * 6 + k) * HH + j0 + 32 * u] = acc[u][k];
    }
    __syncthreads();

    // ctx = ce @ Wv_head
    stage16k(eT, Wv, tid);
    __syncthreads();
    {
        int h = c128 >> 5;
        float acc[6];
        float bvv = bv[c128];
        #pragma unroll
        for (int k = 0; k < 6; k++) acc[k] = bvv;
        const float4* ce4 = (const float4*)qt;
        #pragma unroll 4
        for (int j4 = 0; j4 < 32; j4++) {
            float w0 = eT[(j4 * 4 + 0) * HH + c128];
            float w1 = eT[(j4 * 4 + 1) * HH + c128];
            float w2 = eT[(j4 * 4 + 2) * HH + c128];
            float w3 = eT[(j4 * 4 + 3) * HH + c128];
            #pragma unroll
            for (int k = 0; k < 6; k++) {
                float4 a = ce4[((rh * 6 + k) * NHH + h) * 32 + j4];
                acc[k] += a.x * w0 + a.y * w1 + a.z * w2 + a.w * w3;
            }
        }
        #pragma unroll
        for (int k = 0; k < 6; k++) qb[(rh * 6 + k) * HH + c128] = acc[k];
    }
    __syncthreads();

    // o = ctx @ Wo
    stage16k(eT, Wo, tid);
    __syncthreads();
    {
        float acc[6];
        float bov = bo[c128];
        #pragma unroll
        for (int k = 0; k < 6; k++) acc[k] = bov;
        const float4* cb4 = (const float4*)(qb + rh * 6 * HH);
        #pragma unroll 4
        for (int i4 = 0; i4 < 32; i4++) {
            float w0 = eT[(i4 * 4 + 0) * HH + c128];
            float w1 = eT[(i4 * 4 + 1) * HH + c128];
            float w2 = eT[(i4 * 4 + 2) * HH + c128];
            float w3 = eT[(i4 * 4 + 3) * HH + c128];
            #pragma unroll
            for (int k = 0; k < 6; k++) {
                float4 a = cb4[k * 32 + i4];
                acc[k] += a.x * w0 + a.y * w1 + a.z * w2 + a.w * w3;
            }
        }
        #pragma unroll
        for (int k = 0; k < 6; k++) obuf[(rh * 6 + k) * HH + c128] = acc[k];
    }
    __syncthreads();

    // comb = (query@ctxW1 via folds) + o @ ctxW2 + ctxb -> global
    {
        float acc[6];
        const float* hfo = g_hfold + (size_t)bn * 640 + 512;
        float cbv = ctxb[c128] + hfo[c128];
        #pragma unroll
        for (int k = 0; k < 6; k++)
            acc[k] = cbv + g_sfold[(rh * 6 + k) * 640 + 512 + c128];

        stage16k(eT, ctxW + HH * HH, tid);
        __syncthreads();
        const float4* ob4 = (const float4*)(obuf + rh * 6 * HH);
        #pragma unroll 4
        for (int i4 = 0; i4 < 32; i4++) {
            float w0 = eT[(i4 * 4 + 0) * HH + c128];
            float w1 = eT[(i4 * 4 + 1) * HH + c128];
            float w2 = eT[(i4 * 4 + 2) * HH + c128];
            float w3 = eT[(i4 * 4 + 3) * HH + c128];
            #pragma unroll
            for (int k = 0; k < 6; k++) {
                float4 a = ob4[k * 32 + i4];
                acc[k] += a.x * w0 + a.y * w1 + a.z * w2 + a.w * w3;
            }
        }
        #pragma unroll
        for (int k = 0; k < 6; k++)
            g_comb[((size_t)bn * TT + rh * 6 + k) * HH + c128] = acc[k];
    }
}

// ---------------- LN -> bf16 hi/lo ----------------
__global__ __launch_bounds__(512, 1)
void k_ln(int which, const float* __restrict__ lg, const float* __restrict__ lb) {
    const float* src = which ? g_x1 : g_comb;
    int warp = threadIdx.x >> 5, lane = threadIdx.x & 31;
    int row0 = blockIdx.x * 128;
    for (int it = 0; it < 8; it++) {
        int row = row0 + warp + it * 16;
        float4 x = ((const float4*)(src + (size_t)row * HH))[lane];
        float s1 = x.x + x.y + x.z + x.w;
        #pragma unroll
        for (int off = 16; off > 0; off >>= 1) s1 += __shfl_xor_sync(0xffffffffu, s1, off);
        float mean = s1 * (1.f / HH);
        float dx = x.x - mean, dy = x.y - mean, dz = x.z - mean, dw = x.w - mean;
        float s2 = dx * dx + dy * dy + dz * dz + dw * dw;
        #pragma unroll
        for (int off = 16; off > 0; off >>= 1) s2 += __shfl_xor_sync(0xffffffffu, s2, off);
        float inv = rsqrtf(s2 * (1.f / HH) + 1e-5f);
        float4 gg = ((const float4*)lg)[lane];
        float4 bbv = ((const float4*)lb)[lane];
        float y0 = dx * inv * gg.x + bbv.x;
        float y1 = dy * inv * gg.y + bbv.y;
        float y2 = dz * inv * gg.z + bbv.z;
        float y3 = dw * inv * gg.w + bbv.w;
        float h0 = __bfloat162float(__float2bfloat16(y0));
        float h1 = __bfloat162float(__float2bfloat16(y1));
        float h2 = __bfloat162float(__float2bfloat16(y2));
        float h3 = __bfloat162float(__float2bfloat16(y3));
        size_t o = (size_t)row * 64 + lane * 2;
        g_lnx_hi[o]     = pack_bf(y0, y1);
        g_lnx_hi[o + 1] = pack_bf(y2, y3);
        g_lnx_lo[o]     = pack_bf(y0 - h0, y1 - h1);
        g_lnx_lo[o + 1] = pack_bf(y2 - h2, y3 - h3);
    }
}

// ---------------- HMMA gates GEMM + fused LSTM cell ----------------
// block: 256 thr = 8 warps; 64 rows; N processed in 4 chunks of 128 permuted cols
__global__ __launch_bounds__(256, 2)
void k_gates(int layer, const float* __restrict__ cg) {
    extern __shared__ unsigned su[];
    unsigned* Ah = su + G_AH;
    unsigned* Al = su + G_AL;
    unsigned* Bh = su + G_BH;
    unsigned* Bl = su + G_BL;
    float*    Ds = (float*)(su + G_DS);

    const float* resid = layer ? g_x1 : nullptr;
    float* xout = layer ? g_x2 : g_x1;

    const int tid = threadIdx.x;
    const int row0 = blockIdx.x * 64;
    const int w = tid >> 5, lane = tid & 31;
    const int g = lane >> 2, tg = lane & 3;
    const int mt = w >> 1, nh = w & 1;
    const int qpar = tg & 1;

    // stage A (64 rows of lnx hi/lo), pitch 68
    {
        const uint4* ah4 = (const uint4*)g_lnx_hi + (size_t)row0 * 16;
        const uint4* al4 = (const uint4*)g_lnx_lo + (size_t)row0 * 16;
        for (int i = tid; i < 64 * 16; i += 256) {
            int r = i >> 4, m = i & 15;
            *(uint4*)(Ah + r * GA_PITCH + m * 4) = ah4[r * 16 + m];
            *(uint4*)(Al + r * GA_PITCH + m * 4) = al4[r * 16 + m];
        }
    }
    const uint4* WH = (const uint4*)g_WxT_hi[layer];
    const uint4* WL = (const uint4*)g_WxT_lo[layer];

    for (int nc = 0; nc < 4; nc++) {
        __syncthreads();  // A staged / prev chunk's Ds+B consumed
        // stage B (128 permuted cols x 128 k, hi/lo), pitch 68
        for (int i = tid; i < 128 * 16; i += 256) {
            int r = i >> 4, m = i & 15;
            *(uint4*)(Bh + r * GA_PITCH + m * 4) = WH[(nc * 128 + r) * 16 + m];
            *(uint4*)(Bl + r * GA_PITCH + m * 4) = WL[(nc * 128 + r) * 16 + m];
        }
        __syncthreads();

        float acc[8][4];
        #pragma unroll
        for (int q = 0; q < 8; q++)
            #pragma unroll
            for (int m = 0; m < 4; m++) acc[q][m] = 0.f;

        const int arow = mt * 16 + g;
        #pragma unroll
        for (int kt = 0; kt < 8; kt++) {
            const int ko = kt * 8 + tg;
            unsigned a0h = Ah[arow * GA_PITCH + ko];
            unsigned a1h = Ah[(arow + 8) * GA_PITCH + ko];
            unsigned a2h = Ah[arow * GA_PITCH + ko + 4];
            unsigned a3h = Ah[(arow + 8) * GA_PITCH + ko + 4];
            unsigned a0l = Al[arow * GA_PITCH + ko];
            unsigned a1l = Al[(arow + 8) * GA_PITCH + ko];
            unsigned a2l = Al[arow * GA_PITCH + ko + 4];
            unsigned a3l = Al[(arow + 8) * GA_PITCH + ko + 4];
            #pragma unroll
            for (int q = 0; q < 8; q++) {
                const int nrow = (nh * 8 + q) * 8 + g;  // B col (permuted p, local)
                unsigned b0h = Bh[nrow * GA_PITCH + ko];
                unsigned b1h = Bh[nrow * GA_PITCH + ko + 4];
                unsigned b0l = Bl[nrow * GA_PITCH + ko];
                unsigned b1l = Bl[nrow * GA_PITCH + ko + 4];
                mma16816(acc[q], a0h, a1h, a2h, a3h, b0h, b1h);
                mma16816(acc[q], a0h, a1h, a2h, a3h, b0l, b1l);
                mma16816(acc[q], a0l, a1l, a2l, a3l, b0h, b1h);
            }
        }

        // fused LSTM cell: exchange gate pairs with lane^1
        #pragma unroll
        for (int q = 0; q < 8; q++) {
            float c0 = acc[q][0], c1 = acc[q][1], c2 = acc[q][2], c3 = acc[q][3];
            float r0 = __shfl_xor_sync(0xffffffffu, c0, 1);
            float r1 = __shfl_xor_sync(0xffffffffu, c1, 1);
            float r2 = __shfl_xor_sync(0xffffffffu, c2, 1);
            float r3 = __shfl_xor_sync(0xffffffffu, c3, 1);
            // even tg: row g, own (gi,gf)=c0,c1, recv (gg,go)=r0,r1
            // odd  tg: row g+8, own (gg,go)=c2,c3, recv (gi,gf)=r2,r3
            float gi = qpar ? r2 : c0;
            float gf = qpar ? r3 : c1;
            float gv = qpar ? c2 : r0;
            float go = qpar ? c3 : r1;
            int myrow = mt * 16 + g + 8 * qpar;
            int hhl = (nh * 8 + q) * 2 + (tg >> 1);     // 0..31
            int hh = nc * 32 + hhl;
            int grow = row0 + myrow;
            int bn = grow / TT;
            const float4 ag = *(const float4*)(g_aggWh[layer] + (size_t)bn * 512 + hh * 4);
            gi += ag.x; gf += ag.y; gv += ag.z; go += ag.w;
            float cv = cg[(size_t)bn * HH + hh];
            float cn = sigf(gf) * cv + sigf(gi) * tanhfast(gv);
            float hv = sigf(go) * tanhfast(cn);
            if (resid) hv += resid[(size_t)grow * HH + hh];
            Ds[myrow * 33 + hhl] = hv;
        }
        __syncthreads();

        // coalesced writeback of this chunk: 64 rows x 32 cols
        for (int i = tid; i < 64 * 8; i += 256) {
            int r = i >> 3, m = i & 7;
            const float* d = Ds + r * 33 + m * 4;
            *(float4*)(xout + (size_t)(row0 + r) * HH + nc * 32 + m * 4) =
                make_float4(d[0], d[1], d[2], d[3]);
        }
    }
}

// ---------------- preds ----------------
__global__ __launch_bounds__(512, 1)
void k_preds(const float* __restrict__ outW, const float* __restrict__ outb,
             float* __restrict__ out_pred) {
    int warp = threadIdx.x >> 5, lane = threadIdx.x & 31;
    int row0 = blockIdx.x * 512;
    float4 w = ((const float4*)outW)[lane];
    float ob0 = outb[0];
    for (int it = 0; it < 32; it++) {
        int row = row0 + warp + it * 16;
        float4 x = ((const float4*)(g_x2 + (size_t)row * HH))[lane];
        float acc = x.x * w.x + x.y * w.y + x.z * w.z + x.w * w.w;
        #pragma unroll
        for (int off = 16; off > 0; off >>= 1)
            acc += __shfl_xor_sync(0xffffffffu, acc, off);
        if (lane == 0) {
            int bn = row / TT, t = row % TT;
            int b = bn / NN, n = bn % NN;
            out_pred[((size_t)b * TT + t) * NN + n] = acc + ob0;
        }
    }
}

extern "C" void kernel_launch(void* const* d_in, const int* in_sizes, int n_in,
                              void* d_out, int out_size) {
    const float* enc   = (const float*)d_in[0];
    const float* h0    = (const float*)d_in[1];
    const float* c0    = (const float*)d_in[2];
    const float* h1    = (const float*)d_in[3];
    const float* c1    = (const float*)d_in[4];
    const float* adj   = (const float*)d_in[5];
    const float* stepq = (const float*)d_in[6];
    const float* Wq    = (const float*)d_in[7];
    const float* bq    = (const float*)d_in[8];
    const float* Wk    = (const float*)d_in[9];
    // d_in[10] = bk: softmax-invariant, unused
    const float* Wv    = (const float*)d_in[11];
    const float* bv    = (const float*)d_in[12];
    const float* Wo    = (const float*)d_in[13];
    const float* bo    = (const float*)d_in[14];
    const float* ctxW  = (const float*)d_in[15];
    const float* ctxb  = (const float*)d_in[16];
    const float* Wx0   = (const float*)d_in[17];
    const float* Wh0   = (const float*)d_in[18];
    const float* b0    = (const float*)d_in[19];
    const float* lng0  = (const float*)d_in[20];
    const float* lnb0  = (const float*)d_in[21];
    const float* Wx1   = (const float*)d_in[22];
    const float* Wh1   = (const float*)d_in[23];
    const float* b1    = (const float*)d_in[24];
    const float* lng1  = (const float*)d_in[25];
    const float* lnb1  = (const float*)d_in[26];
    const float* outW  = (const float*)d_in[27];
    const float* outb  = (const float*)d_in[28];

    float* out      = (float*)d_out;
    float* out_pred = out;
    float* out_attn = out + (size_t)BB * TT * NN;

    cudaFuncSetAttribute(k_attn, cudaFuncAttributeMaxDynamicSharedMemorySize, SMEM_BYTES);
    cudaFuncSetAttribute(k_agg, cudaFuncAttributeMaxDynamicSharedMemorySize, AGG_SMEM);
    cudaFuncSetAttribute(k_aggWh, cudaFuncAttributeMaxDynamicSharedMemorySize, AGG_SMEM);
    cudaFuncSetAttribute(k_gates, cudaFuncAttributeMaxDynamicSharedMemorySize, G_SMEM_BYTES);

    k_w2<<<320, 256>>>(Wq, Wk, ctxW, bq);
    k_wprep<<<512, 256>>>(Wx0, Wx1);
    k_fold<<<(BB * NN + TT) / 8, 640>>>(h1, stepq);
    k_agg<<<5 * 2 * BB, 512, AGG_SMEM>>>(h0, h1, adj);
    k_aggWh<<<4 * 2 * BB, 512, AGG_SMEM>>>(Wh0, b0, Wh1, b1);
    k_attn<<<BB * NN, 512, SMEM_BYTES>>>(enc, Wv, bv, Wo, bo, ctxW, ctxb, out_attn);
    k_ln<<<NROWS / 128, 512>>>(0, lng0, lnb0);
    k_gates<<<NROWS / 64, 256, G_SMEM_BYTES>>>(0, c0);
    k_ln<<<NROWS / 128, 512>>>(1, lng1, lnb1);
    k_gates<<<NROWS / 64, 256, G_SMEM_BYTES>>>(1, c1);
    k_preds<<<NROWS / 512, 512>>>(outW, outb, out_pred);
}

// round 12
// speedup vs baseline: 2.5570x; 1.0647x over previous
#include <cuda_runtime.h>
#include <cuda_bf16.h>
#include <cstdint>

#define BB  16
#define SS  168
#define NN  200
#define HH  128
#define TT  24
#define NHH 4
#define DHH 32
#define NROWS (BB * NN * TT)   // 76800

#define AGG_SMEM (NN * HH * 4)

// ---- k_attn v2 smem map (u32/float units) ----
#define QT_P   68
#define A_QTH  0
#define A_QTL  6528
#define A_ESJH 13056
#define A_ESJL 24480
#define EJ_P   90
#define A_EJSH 13056
#define A_EJSL 24576
#define SC_P   180
#define A_SC   36096
#define CE_P   136
#define A_CE   0
#define A_WSTG 13056
#define A_OBUF 36096
#define A_CTX  39168
#define ATTN_FLOATS 53376
#define ATTN_SMEM_BYTES (ATTN_FLOATS * 4)   // 213504

// k_gates smem layout (unsigned units, pitch 68)
#define GA_PITCH 68
#define G_AH  0
#define G_AL  (G_AH + 64 * GA_PITCH)
#define G_BH  (G_AL + 64 * GA_PITCH)
#define G_BL  (G_BH + 128 * GA_PITCH)
#define G_DS  (G_BL + 128 * GA_PITCH)
#define G_SMEM_BYTES ((G_DS + 64 * 33) * 4)   // 112896

// ---------------- device scratch ----------------
__device__ float g_W2[HH * 640];
__device__ float g_bqk[512];
__device__ float g_hfold[(size_t)BB * NN * 640];
__device__ float g_sfold[TT * 640];
__device__ float g_agg[2][BB * NN * HH];
__device__ float g_aggWh[2][BB * NN * 4 * HH];   // PERMUTED cols: p = hh*4 + gate
__device__ float g_comb[(size_t)NROWS * HH];
__device__ float g_x1[(size_t)NROWS * HH];
__device__ float g_x2[(size_t)NROWS * HH];
__device__ unsigned g_lnx_hi[(size_t)NROWS * 64];
__device__ unsigned g_lnx_lo[(size_t)NROWS * 64];
__device__ __nv_bfloat16 g_WxT_hi[2][512 * 128];
__device__ __nv_bfloat16 g_WxT_lo[2][512 * 128];

__device__ __forceinline__ float sigf(float x) {
    return __fdividef(1.f, 1.f + __expf(fminf(-x, 80.f)));
}
__device__ __forceinline__ float tanhfast(float x) {
    float e = __expf(fminf(2.f * x, 80.f));
    return __fdividef(e - 1.f, e + 1.f);
}
__device__ __forceinline__ unsigned pack_bf(float lo, float hi) {
    unsigned r;
    asm("cvt.rn.bf16x2.f32 %0, %1, %2;" : "=r"(r) : "f"(hi), "f"(lo));
    return r;
}
__device__ __forceinline__ void split2(float a, float b, unsigned& h, unsigned& l) {
    h = pack_bf(a, b);
    __nv_bfloat162 hb = *(__nv_bfloat162*)&h;
    l = pack_bf(a - __bfloat162float(hb.x), b - __bfloat162float(hb.y));
}
// HMMA m16n8k16 bf16 -> fp32 (family-portable)
__device__ __forceinline__ void mma16816(float* c, unsigned a0, unsigned a1,
                                         unsigned a2, unsigned a3,
                                         unsigned b0, unsigned b1) {
    asm volatile(
        "mma.sync.aligned.m16n8k16.row.col.f32.bf16.bf16.f32 "
        "{%0,%1,%2,%3}, {%4,%5,%6,%7}, {%8,%9}, {%0,%1,%2,%3};"
        : "+f"(c[0]), "+f"(c[1]), "+f"(c[2]), "+f"(c[3])
        : "r"(a0), "r"(a1), "r"(a2), "r"(a3), "r"(b0), "r"(b1));
}

// ---------------- prep kernels (unchanged from R11) ----------------
__global__ void k_w2(const float* __restrict__ Wq, const float* __restrict__ Wk,
                     const float* __restrict__ ctxW, const float* __restrict__ bq) {
    int idx = blockIdx.x * 256 + threadIdx.x;
    int i = idx / 640, col = idx % 640;
    if (i < HH) {
        float acc;
        if (col < 512) {
            int h = col >> 7, j = col & 127;
            acc = 0.f;
            #pragma unroll 8
            for (int d = 0; d < 32; d++)
                acc += Wq[i * HH + h * 32 + d] * Wk[j * HH + h * 32 + d];
        } else {
            acc = ctxW[i * HH + (col - 512)];
        }
        g_W2[i * 640 + col] = acc;
    }
    if (idx < 512) {
        int h = idx >> 7, j = idx & 127;
        float a = 0.f;
        #pragma unroll 8
        for (int d = 0; d < 32; d++)
            a += bq[h * 32 + d] * Wk[j * HH + h * 32 + d];
        g_bqk[idx] = a;
    }
}

__global__ void k_wprep(const float* __restrict__ Wx0, const float* __restrict__ Wx1) {
    int idx = blockIdx.x * 256 + threadIdx.x;
    if (idx >= 2 * 512 * 128) return;
    int l = idx / (512 * 128);
    int rem = idx % (512 * 128);
    int p = rem / 128, i = rem % 128;
    const float* Wx = l ? Wx1 : Wx0;
    float v = Wx[i * 512 + (p & 3) * 128 + (p >> 2)];
    __nv_bfloat16 hi = __float2bfloat16(v);
    float lo = v - __bfloat162float(hi);
    g_WxT_hi[l][p * 128 + i] = hi;
    g_WxT_lo[l][p * 128 + i] = __float2bfloat16(lo);
}

__global__ __launch_bounds__(640, 1)
void k_fold(const float* __restrict__ h1, const float* __restrict__ stepq) {
    __shared__ float aS[8 * HH];
    int r0 = blockIdx.x * 8;
    bool isq = (r0 >= BB * NN);
    const float* src = isq ? (stepq + (r0 - BB * NN) * HH) : (h1 + (size_t)r0 * HH);
    for (int idx = threadIdx.x; idx < 8 * HH; idx += 640) aS[idx] = src[idx];
    __syncthreads();
    int c = threadIdx.x;
    float acc[8];
    float binit = (isq && c < 512) ? g_bqk[c] : 0.f;
    #pragma unroll
    for (int k = 0; k < 8; k++) acc[k] = binit;
    #pragma unroll 4
    for (int i = 0; i < HH; i++) {
        float w = g_W2[i * 640 + c];
        #pragma unroll
        for (int k = 0; k < 8; k++) acc[k] += aS[k * HH + i] * w;
    }
    float* dst = isq ? (g_sfold + (r0 - BB * NN) * 640) : (g_hfold + (size_t)r0 * 640);
    #pragma unroll
    for (int k = 0; k < 8; k++) dst[k * 640 + c] = acc[k];
}

__global__ __launch_bounds__(512, 1)
void k_agg(const float* __restrict__ h0, const float* __restrict__ h1,
           const float* __restrict__ adj) {
    extern __shared__ float hS[];
    int c5 = blockIdx.x / 32;
    int lb = blockIdx.x % 32;
    int l = lb >> 4, b = lb & 15;
    const float* hsrc = (l ? h1 : h0) + (size_t)b * NN * HH;
    for (int idx = threadIdx.x; idx < NN * HH; idx += 512) hS[idx] = hsrc[idx];
    __syncthreads();
    int hh = threadIdx.x & 127, g = threadIdx.x >> 7;
    const float4* adj4 = (const float4*)adj;
    int n0 = g * 50 + c5 * 10;
    float acc[10];
    #pragma unroll
    for (int k = 0; k < 10; k++) acc[k] = 0.f;
    for (int m4 = 0; m4 < 50; m4++) {
        float4 av[10];
        #pragma unroll
        for (int k = 0; k < 10; k++) av[k] = adj4[(n0 + k) * 50 + m4];
        #pragma unroll
        for (int u = 0; u < 4; u++) {
            float hv = hS[(m4 * 4 + u) * HH + hh];
            #pragma unroll
            for (int k = 0; k < 10; k++)
                acc[k] += ((const float*)&av[k])[u] * hv;
        }
    }
    #pragma unroll
    for (int k = 0; k < 10; k++)
        g_agg[l][((size_t)b * NN + n0 + k) * HH + hh] = acc[k];
}

__global__ __launch_bounds__(512, 1)
void k_aggWh(const float* __restrict__ Wh0, const float* __restrict__ bb0,
             const float* __restrict__ Wh1, const float* __restrict__ bb1) {
    extern __shared__ float aggS[];
    int ch = blockIdx.x >> 5;
    int lb = blockIdx.x & 31;
    int l = lb >> 4, b = lb & 15;
    const float* Wh   = l ? Wh1 : Wh0;
    const float* bias = l ? bb1 : bb0;
    const float* asrc = g_agg[l] + (size_t)b * NN * HH;
    for (int idx = threadIdx.x; idx < NN * HH; idx += 512) aggS[idx] = asrc[idx];
    __syncthreads();
    int c = threadIdx.x;
    int perm = (c & 127) * 4 + (c >> 7);
    float bsv = bias[c];
    const float4* a4 = (const float4*)aggS;
    float* dst = g_aggWh[l] + (size_t)b * NN * 4 * HH;
    int n0 = ch * 50;
    float acc[50];
    #pragma unroll
    for (int k = 0; k < 50; k++) acc[k] = bsv;
    for (int i4 = 0; i4 < 32; i4++) {
        float w0 = Wh[(i4 * 4 + 0) * 512 + c];
        float w1 = Wh[(i4 * 4 + 1) * 512 + c];
        float w2 = Wh[(i4 * 4 + 2) * 512 + c];
        float w3 = Wh[(i4 * 4 + 3) * 512 + c];
        #pragma unroll
        for (int k = 0; k < 50; k++) {
            float4 a = a4[(n0 + k) * 32 + i4];
            acc[k] += a.x * w0 + a.y * w1 + a.z * w2 + a.w * w3;
        }
    }
    #pragma unroll
    for (int k = 0; k < 50; k++) dst[(n0 + k) * 512 + perm] = acc[k];
}

__device__ __forceinline__ void stage16k(float* __restrict__ dst,
                                         const float* __restrict__ src, int tid) {
    const float4* s4 = (const float4*)src;
    float4* d4 = (float4*)dst;
    #pragma unroll
    for (int i = 0; i < 8; i++) d4[tid + 512 * i] = s4[tid + 512 * i];
}

// ---------------- attention megakernel v2 (HMMA scores + ce) ----------------
__global__ __launch_bounds__(512, 1)
void k_attn(const float* __restrict__ enc,
            const float* __restrict__ Wv,   const float* __restrict__ bv,
            const float* __restrict__ Wo,   const float* __restrict__ bo,
            const float* __restrict__ ctxW, const float* __restrict__ ctxb,
            float* __restrict__ out_attn)
{
    extern __shared__ float sm[];
    unsigned* su = (unsigned*)sm;
    float* sc = sm + A_SC;

    const int tid = threadIdx.x;
    const int b = blockIdx.x / NN, n = blockIdx.x % NN;
    const int bn = b * NN + n;
    const int w = tid >> 5, lane = tid & 31;
    const int g = lane >> 2, tg = lane & 3;

    // ---- P0: e_sj bf16 h/l + qt bf16 h/l ----
    {
        const float4* e4 = (const float4*)enc;
        for (int idx = tid; idx < SS * 32; idx += 512) {
            int s = idx >> 5, j4 = idx & 31;
            float4 v = e4[((size_t)(b * SS + s) * NN + n) * 32 + j4];
            unsigned h0, l0, h1, l1;
            split2(v.x, v.y, h0, l0);
            split2(v.z, v.w, h1, l1);
            unsigned* dh = su + A_ESJH + s * QT_P + j4 * 2;
            unsigned* dl = su + A_ESJL + s * QT_P + j4 * 2;
            dh[0] = h0; dh[1] = h1;
            dl[0] = l0; dl[1] = l1;
        }
        const float4* sf4 = (const float4*)g_sfold;
        const float4* hf4 = (const float4*)(g_hfold + (size_t)bn * 640);
        for (int idx = tid; idx < 96 * 32; idx += 512) {
            int r = idx >> 5, j4 = idx & 31;   // r = t*4+h; fold col = h*128 + j
            int t = r >> 2;
            float4 sa = sf4[t * 160 + (r & 3) * 32 + j4];
            float4 hb = hf4[(r & 3) * 32 + j4];
            unsigned h0, l0, h1, l1;
            split2(sa.x + hb.x, sa.y + hb.y, h0, l0);
            split2(sa.z + hb.z, sa.w + hb.w, h1, l1);
            unsigned* dh = su + A_QTH + r * QT_P + j4 * 2;
            unsigned* dl = su + A_QTL + r * QT_P + j4 * 2;
            dh[0] = h0; dh[1] = h1;
            dl[0] = l0; dl[1] = l1;
        }
    }
    __syncthreads();

    // ---- P3: scores = qt @ e^T  (HMMA, 6 mtiles x 21 ntiles) ----
    {
        const float scale = 0.17677669529663687f;
        for (int job = w; job < 126; job += 16) {
            int mt = job / 21, nt = job % 21;
            float acc[4] = {0.f, 0.f, 0.f, 0.f};
            int ra = (mt * 16 + g) * QT_P;
            int rb = (nt * 8 + g) * QT_P;
            #pragma unroll
            for (int kt = 0; kt < 8; kt++) {
                int ko = kt * 8 + tg;
                unsigned a0h = su[A_QTH + ra + ko];
                unsigned a1h = su[A_QTH + ra + 8 * QT_P + ko];
                unsigned a2h = su[A_QTH + ra + ko + 4];
                unsigned a3h = su[A_QTH + ra + 8 * QT_P + ko + 4];
                unsigned a0l = su[A_QTL + ra + ko];
                unsigned a1l = su[A_QTL + ra + 8 * QT_P + ko];
                unsigned a2l = su[A_QTL + ra + ko + 4];
                unsigned a3l = su[A_QTL + ra + 8 * QT_P + ko + 4];
                unsigned b0h = su[A_ESJH + rb + ko];
                unsigned b1h = su[A_ESJH + rb + ko + 4];
                unsigned b0l = su[A_ESJL + rb + ko];
                unsigned b1l = su[A_ESJL + rb + ko + 4];
                mma16816(acc, a0h, a1h, a2h, a3h, b0h, b1h);
                mma16816(acc, a0h, a1h, a2h, a3h, b0l, b1l);
                mma16816(acc, a0l, a1l, a2l, a3l, b0h, b1h);
            }
            int row = mt * 16 + g, col = nt * 8 + 2 * tg;
            *(float2*)&sc[row * SC_P + col]       = make_float2(acc[0] * scale, acc[1] * scale);
            *(float2*)&sc[(row + 8) * SC_P + col] = make_float2(acc[2] * scale, acc[3] * scale);
        }
    }
    __syncthreads();

    // ---- load e_js bf16 h/l (overwrites qt-dead? no: e_sj region) ----
    {
        const float* eb = enc + ((size_t)b * SS * NN + n) * HH;
        for (int idx = tid; idx < 128 * 90; idx += 512) {
            int j = idx & 127, sp = idx >> 7;
            unsigned h, l;
            if (sp < 84) {
                float v0 = eb[(size_t)(2 * sp) * NN * HH + j];
                float v1 = eb[(size_t)(2 * sp + 1) * NN * HH + j];
                split2(v0, v1, h, l);
            } else { h = 0u; l = 0u; }
            su[A_EJSH + j * EJ_P + sp] = h;
            su[A_EJSL + j * EJ_P + sp] = l;
        }
    }

    // ---- P4: softmax (fp32, exact) + attn out + zero pad ----
    {
        for (int r = w; r < 96; r += 16) {
            float v[6];
            float mx = -1e30f;
            #pragma unroll
            for (int u = 0; u < 6; u++) {
                int s = lane + 32 * u;
                v[u] = (s < SS) ? sc[r * SC_P + s] : -1e30f;
                mx = fmaxf(mx, v[u]);
            }
            #pragma unroll
            for (int off = 16; off > 0; off >>= 1)
                mx = fmaxf(mx, __shfl_xor_sync(0xffffffffu, mx, off));
            float sum = 0.f;
            #pragma unroll
            for (int u = 0; u < 6; u++) {
                int s = lane + 32 * u;
                if (s < SS) { v[u] = __expf(v[u] - mx); sum += v[u]; }
            }
            #pragma unroll
            for (int off = 16; off > 0; off >>= 1)
                sum += __shfl_xor_sync(0xffffffffu, sum, off);
            float inv = __fdividef(1.f, sum);
            int t = r >> 2, h = r & 3;
            float* gout = out_attn + ((((size_t)b * TT + t) * NHH + h) * NN + n) * SS;
            #pragma unroll
            for (int u = 0; u < 6; u++) {
                int s = lane + 32 * u;
                if (s < SS) {
                    float a = v[u] * inv;
                    sc[r * SC_P + s] = a;
                    gout[s] = a;
                }
            }
            if (lane < 8) sc[r * SC_P + SS + lane] = 0.f;   // pad s=168..175
        }
    }
    __syncthreads();

    // ---- P5: ce = attn @ e  (HMMA, A-frags built from fp32 attn) ----
    {
        float* ce = sm + A_CE;
        for (int job = w; job < 96; job += 16) {
            int mt = job / 16, nt = job % 16;
            float acc[4] = {0.f, 0.f, 0.f, 0.f};
            const float* arow0 = sc + (mt * 16 + g) * SC_P;
            const float* arow1 = arow0 + 8 * SC_P;
            int rb = (nt * 8 + g) * EJ_P;
            #pragma unroll
            for (int kt = 0; kt < 11; kt++) {
                int ko = kt * 8 + tg;
                float2 p0 = *(const float2*)&arow0[2 * ko];
                float2 p1 = *(const float2*)&arow1[2 * ko];
                float2 p2 = *(const float2*)&arow0[2 * (ko + 4)];
                float2 p3 = *(const float2*)&arow1[2 * (ko + 4)];
                unsigned a0h, a0l, a1h, a1l, a2h, a2l, a3h, a3l;
                split2(p0.x, p0.y, a0h, a0l);
                split2(p1.x, p1.y, a1h, a1l);
                split2(p2.x, p2.y, a2h, a2l);
                split2(p3.x, p3.y, a3h, a3l);
                unsigned b0h = su[A_EJSH + rb + ko];
                unsigned b1h = su[A_EJSH + rb + ko + 4];
                unsigned b0l = su[A_EJSL + rb + ko];
                unsigned b1l = su[A_EJSL + rb + ko + 4];
                mma16816(acc, a0h, a1h, a2h, a3h, b0h, b1h);
                mma16816(acc, a0h, a1h, a2h, a3h, b0l, b1l);
                mma16816(acc, a0l, a1l, a2l, a3l, b0h, b1h);
            }
            int row = mt * 16 + g, col = nt * 8 + 2 * tg;
            *(float2*)&ce[row * CE_P + col]       = make_float2(acc[0], acc[1]);
            *(float2*)&ce[(row + 8) * CE_P + col] = make_float2(acc[2], acc[3]);
        }
    }
    __syncthreads();

    const int c128 = tid & 127, rh = tid >> 7;
    float* wst  = sm + A_WSTG;
    float* obuf = sm + A_OBUF;
    float* ctxb_ = sm + A_CTX;

    // ---- P6: ctx = ce @ Wv(head rows) + bv ----
    stage16k(wst, Wv, tid);
    __syncthreads();
    {
        int h = c128 >> 5;
        float acc[6];
        float bvv = bv[c128];
        #pragma unroll
        for (int k = 0; k < 6; k++) acc[k] = bvv;
        const float4* ce4 = (const float4*)(sm + A_CE);
        #pragma unroll 4
        for (int j4 = 0; j4 < 32; j4++) {
            float w0 = wst[(j4 * 4 + 0) * HH + c128];
            float w1 = wst[(j4 * 4 + 1) * HH + c128];
            float w2 = wst[(j4 * 4 + 2) * HH + c128];
            float w3 = wst[(j4 * 4 + 3) * HH + c128];
            #pragma unroll
            for (int k = 0; k < 6; k++) {
                float4 a = ce4[(((rh * 6 + k) * 4 + h) * 34) + j4];
                acc[k] += a.x * w0 + a.y * w1 + a.z * w2 + a.w * w3;
            }
        }
        #pragma unroll
        for (int k = 0; k < 6; k++) ctxb_[(rh * 6 + k) * HH + c128] = acc[k];
    }
    __syncthreads();

    // ---- P7: o = ctx @ Wo + bo ----
    stage16k(wst, Wo, tid);
    __syncthreads();
    {
        float acc[6];
        float bov = bo[c128];
        #pragma unroll
        for (int k = 0; k < 6; k++) acc[k] = bov;
        const float4* cb4 = (const float4*)(ctxb_ + rh * 6 * HH);
        #pragma unroll 4
        for (int i4 = 0; i4 < 32; i4++) {
            float w0 = wst[(i4 * 4 + 0) * HH + c128];
            float w1 = wst[(i4 * 4 + 1) * HH + c128];
            float w2 = wst[(i4 * 4 + 2) * HH + c128];
            float w3 = wst[(i4 * 4 + 3) * HH + c128];
            #pragma unroll
            for (int k = 0; k < 6; k++) {
                float4 a = cb4[k * 32 + i4];
                acc[k] += a.x * w0 + a.y * w1 + a.z * w2 + a.w * w3;
            }
        }
        #pragma unroll
        for (int k = 0; k < 6; k++) obuf[(rh * 6 + k) * HH + c128] = acc[k];
    }
    __syncthreads();

    // ---- P8: comb = (query@ctxW1 via folds) + o @ ctxW2 + ctxb -> global ----
    {
        float acc[6];
        const float* hfo = g_hfold + (size_t)bn * 640 + 512;
        float cbv = ctxb[c128] + hfo[c128];
        #pragma unroll
        for (int k = 0; k < 6; k++)
            acc[k] = cbv + g_sfold[(rh * 6 + k) * 640 + 512 + c128];

        stage16k(wst, ctxW + HH * HH, tid);
        __syncthreads();
        const float4* ob4 = (const float4*)(obuf + rh * 6 * HH);
        #pragma unroll 4
        for (int i4 = 0; i4 < 32; i4++) {
            float w0 = wst[(i4 * 4 + 0) * HH + c128];
            float w1 = wst[(i4 * 4 + 1) * HH + c128];
            float w2 = wst[(i4 * 4 + 2) * HH + c128];
            float w3 = wst[(i4 * 4 + 3) * HH + c128];
            #pragma unroll
            for (int k = 0; k < 6; k++) {
                float4 a = ob4[k * 32 + i4];
                acc[k] += a.x * w0 + a.y * w1 + a.z * w2 + a.w * w3;
            }
        }
        #pragma unroll
        for (int k = 0; k < 6; k++)
            g_comb[((size_t)bn * TT + rh * 6 + k) * HH + c128] = acc[k];
    }
}

// ---------------- LN -> bf16 hi/lo ----------------
__global__ __launch_bounds__(512, 1)
void k_ln(int which, const float* __restrict__ lg, const float* __restrict__ lb) {
    const float* src = which ? g_x1 : g_comb;
    int warp = threadIdx.x >> 5, lane = threadIdx.x & 31;
    int row0 = blockIdx.x * 128;
    for (int it = 0; it < 8; it++) {
        int row = row0 + warp + it * 16;
        float4 x = ((const float4*)(src + (size_t)row * HH))[lane];
        float s1 = x.x + x.y + x.z + x.w;
        #pragma unroll
        for (int off = 16; off > 0; off >>= 1) s1 += __shfl_xor_sync(0xffffffffu, s1, off);
        float mean = s1 * (1.f / HH);
        float dx = x.x - mean, dy = x.y - mean, dz = x.z - mean, dw = x.w - mean;
        float s2 = dx * dx + dy * dy + dz * dz + dw * dw;
        #pragma unroll
        for (int off = 16; off > 0; off >>= 1) s2 += __shfl_xor_sync(0xffffffffu, s2, off);
        float inv = rsqrtf(s2 * (1.f / HH) + 1e-5f);
        float4 gg = ((const float4*)lg)[lane];
        float4 bbv = ((const float4*)lb)[lane];
        float y0 = dx * inv * gg.x + bbv.x;
        float y1 = dy * inv * gg.y + bbv.y;
        float y2 = dz * inv * gg.z + bbv.z;
        float y3 = dw * inv * gg.w + bbv.w;
        size_t o = (size_t)row * 64 + lane * 2;
        unsigned h0, l0, h1, l1;
        split2(y0, y1, h0, l0);
        split2(y2, y3, h1, l1);
        g_lnx_hi[o] = h0; g_lnx_hi[o + 1] = h1;
        g_lnx_lo[o] = l0; g_lnx_lo[o + 1] = l1;
    }
}

// ---------------- HMMA gates GEMM + fused LSTM cell (unchanged) ----------------
__global__ __launch_bounds__(256, 2)
void k_gates(int layer, const float* __restrict__ cg) {
    extern __shared__ unsigned su[];
    unsigned* Ah = su + G_AH;
    unsigned* Al = su + G_AL;
    unsigned* Bh = su + G_BH;
    unsigned* Bl = su + G_BL;
    float*    Ds = (float*)(su + G_DS);

    const float* resid = layer ? g_x1 : nullptr;
    float* xout = layer ? g_x2 : g_x1;

    const int tid = threadIdx.x;
    const int row0 = blockIdx.x * 64;
    const int w = tid >> 5, lane = tid & 31;
    const int g = lane >> 2, tg = lane & 3;
    const int mt = w >> 1, nh = w & 1;
    const int qpar = tg & 1;

    {
        const uint4* ah4 = (const uint4*)g_lnx_hi + (size_t)row0 * 16;
        const uint4* al4 = (const uint4*)g_lnx_lo + (size_t)row0 * 16;
        for (int i = tid; i < 64 * 16; i += 256) {
            int r = i >> 4, m = i & 15;
            *(uint4*)(Ah + r * GA_PITCH + m * 4) = ah4[r * 16 + m];
            *(uint4*)(Al + r * GA_PITCH + m * 4) = al4[r * 16 + m];
        }
    }
    const uint4* WH = (const uint4*)g_WxT_hi[layer];
    const uint4* WL = (const uint4*)g_WxT_lo[layer];

    for (int nc = 0; nc < 4; nc++) {
        __syncthreads();
        for (int i = tid; i < 128 * 16; i += 256) {
            int r = i >> 4, m = i & 15;
            *(uint4*)(Bh + r * GA_PITCH + m * 4) = WH[(nc * 128 + r) * 16 + m];
            *(uint4*)(Bl + r * GA_PITCH + m * 4) = WL[(nc * 128 + r) * 16 + m];
        }
        __syncthreads();

        float acc[8][4];
        #pragma unroll
        for (int q = 0; q < 8; q++)
            #pragma unroll
            for (int m = 0; m < 4; m++) acc[q][m] = 0.f;

        const int arow = mt * 16 + g;
        #pragma unroll
        for (int kt = 0; kt < 8; kt++) {
            const int ko = kt * 8 + tg;
            unsigned a0h = Ah[arow * GA_PITCH + ko];
            unsigned a1h = Ah[(arow + 8) * GA_PITCH + ko];
            unsigned a2h = Ah[arow * GA_PITCH + ko + 4];
            unsigned a3h = Ah[(arow + 8) * GA_PITCH + ko + 4];
            unsigned a0l = Al[arow * GA_PITCH + ko];
            unsigned a1l = Al[(arow + 8) * GA_PITCH + ko];
            unsigned a2l = Al[arow * GA_PITCH + ko + 4];
            unsigned a3l = Al[(arow + 8) * GA_PITCH + ko + 4];
            #pragma unroll
            for (int q = 0; q < 8; q++) {
                const int nrow = (nh * 8 + q) * 8 + g;
                unsigned b0h = Bh[nrow * GA_PITCH + ko];
                unsigned b1h = Bh[nrow * GA_PITCH + ko + 4];
                unsigned b0l = Bl[nrow * GA_PITCH + ko];
                unsigned b1l = Bl[nrow * GA_PITCH + ko + 4];
                mma16816(acc[q], a0h, a1h, a2h, a3h, b0h, b1h);
                mma16816(acc[q], a0h, a1h, a2h, a3h, b0l, b1l);
                mma16816(acc[q], a0l, a1l, a2l, a3l, b0h, b1h);
            }
        }

        #pragma unroll
        for (int q = 0; q < 8; q++) {
            float c0 = acc[q][0], c1 = acc[q][1], c2 = acc[q][2], c3 = acc[q][3];
            float r0 = __shfl_xor_sync(0xffffffffu, c0, 1);
            float r1 = __shfl_xor_sync(0xffffffffu, c1, 1);
            float r2 = __shfl_xor_sync(0xffffffffu, c2, 1);
            float r3 = __shfl_xor_sync(0xffffffffu, c3, 1);
            float gi = qpar ? r2 : c0;
            float gf = qpar ? r3 : c1;
            float gv = qpar ? c2 : r0;
            float go = qpar ? c3 : r1;
            int myrow = mt * 16 + g + 8 * qpar;
            int hhl = (nh * 8 + q) * 2 + (tg >> 1);
            int hh = nc * 32 + hhl;
            int grow = row0 + myrow;
            int bn = grow / TT;
            const float4 ag = *(const float4*)(g_aggWh[layer] + (size_t)bn * 512 + hh * 4);
            gi += ag.x; gf += ag.y; gv += ag.z; go += ag.w;
            float cv = cg[(size_t)bn * HH + hh];
            float cn = sigf(gf) * cv + sigf(gi) * tanhfast(gv);
            float hv = sigf(go) * tanhfast(cn);
            if (resid) hv += resid[(size_t)grow * HH + hh];
            Ds[myrow * 33 + hhl] = hv;
        }
        __syncthreads();

        for (int i = tid; i < 64 * 8; i += 256) {
            int r = i >> 3, m = i & 7;
            const float* d = Ds + r * 33 + m * 4;
            *(float4*)(xout + (size_t)(row0 + r) * HH + nc * 32 + m * 4) =
                make_float4(d[0], d[1], d[2], d[3]);
        }
    }
}

// ---------------- preds ----------------
__global__ __launch_bounds__(512, 1)
void k_preds(const float* __restrict__ outW, const float* __restrict__ outb,
             float* __restrict__ out_pred) {
    int warp = threadIdx.x >> 5, lane = threadIdx.x & 31;
    int row0 = blockIdx.x * 512;
    float4 w = ((const float4*)outW)[lane];
    float ob0 = outb[0];
    for (int it = 0; it < 32; it++) {
        int row = row0 + warp + it * 16;
        float4 x = ((const float4*)(g_x2 + (size_t)row * HH))[lane];
        float acc = x.x * w.x + x.y * w.y + x.z * w.z + x.w * w.w;
        #pragma unroll
        for (int off = 16; off > 0; off >>= 1)
            acc += __shfl_xor_sync(0xffffffffu, acc, off);
        if (lane == 0) {
            int bn = row / TT, t = row % TT;
            int b = bn / NN, n = bn % NN;
            out_pred[((size_t)b * TT + t) * NN + n] = acc + ob0;
        }
    }
}

extern "C" void kernel_launch(void* const* d_in, const int* in_sizes, int n_in,
                              void* d_out, int out_size) {
    const float* enc   = (const float*)d_in[0];
    const float* h0    = (const float*)d_in[1];
    const float* c0    = (const float*)d_in[2];
    const float* h1    = (const float*)d_in[3];
    const float* c1    = (const float*)d_in[4];
    const float* adj   = (const float*)d_in[5];
    const float* stepq = (const float*)d_in[6];
    const float* Wq    = (const float*)d_in[7];
    const float* bq    = (const float*)d_in[8];
    const float* Wk    = (const float*)d_in[9];
    // d_in[10] = bk: softmax-invariant, unused
    const float* Wv    = (const float*)d_in[11];
    const float* bv    = (const float*)d_in[12];
    const float* Wo    = (const float*)d_in[13];
    const float* bo    = (const float*)d_in[14];
    const float* ctxW  = (const float*)d_in[15];
    const float* ctxb  = (const float*)d_in[16];
    const float* Wx0   = (const float*)d_in[17];
    const float* Wh0   = (const float*)d_in[18];
    const float* b0    = (const float*)d_in[19];
    const float* lng0  = (const float*)d_in[20];
    const float* lnb0  = (const float*)d_in[21];
    const float* Wx1   = (const float*)d_in[22];
    const float* Wh1   = (const float*)d_in[23];
    const float* b1    = (const float*)d_in[24];
    const float* lng1  = (const float*)d_in[25];
    const float* lnb1  = (const float*)d_in[26];
    const float* outW  = (const float*)d_in[27];
    const float* outb  = (const float*)d_in[28];

    float* out      = (float*)d_out;
    float* out_pred = out;
    float* out_attn = out + (size_t)BB * TT * NN;

    cudaFuncSetAttribute(k_attn, cudaFuncAttributeMaxDynamicSharedMemorySize, ATTN_SMEM_BYTES);
    cudaFuncSetAttribute(k_agg, cudaFuncAttributeMaxDynamicSharedMemorySize, AGG_SMEM);
    cudaFuncSetAttribute(k_aggWh, cudaFuncAttributeMaxDynamicSharedMemorySize, AGG_SMEM);
    cudaFuncSetAttribute(k_gates, cudaFuncAttributeMaxDynamicSharedMemorySize, G_SMEM_BYTES);

    k_w2<<<320, 256>>>(Wq, Wk, ctxW, bq);
    k_wprep<<<512, 256>>>(Wx0, Wx1);
    k_fold<<<(BB * NN + TT) / 8, 640>>>(h1, stepq);
    k_agg<<<5 * 2 * BB, 512, AGG_SMEM>>>(h0, h1, adj);
    k_aggWh<<<4 * 2 * BB, 512, AGG_SMEM>>>(Wh0, b0, Wh1, b1);
    k_attn<<<BB * NN, 512, ATTN_SMEM_BYTES>>>(enc, Wv, bv, Wo, bo, ctxW, ctxb, out_attn);
    k_ln<<<NROWS / 128, 512>>>(0, lng0, lnb0);
    k_gates<<<NROWS / 64, 256, G_SMEM_BYTES>>>(0, c0);
    k_ln<<<NROWS / 128, 512>>>(1, lng1, lnb1);
    k_gates<<<NROWS / 64, 256, G_SMEM_BYTES>>>(1, c1);
    k_preds<<<NROWS / 512, 512>>>(outW, outb, out_pred);
}

// round 13
// speedup vs baseline: 2.8612x; 1.1190x over previous
#include <cuda_runtime.h>
#include <cuda_bf16.h>
#include <cstdint>

#define BB  16
#define SS  168
#define NN  200
#define HH  128
#define TT  24
#define NHH 4
#define DHH 32
#define NROWS (BB * NN * TT)   // 76800

#define AGG_SMEM (NN * HH * 4)

// ---- k_attn v3 smem map (u32/float units) ----
#define QT_P   68
#define A_QTH  0
#define A_QTL  6528
#define A_ESJH 13056
#define A_ESJL 24480
#define EJ_P   90
#define A_EJSH 13056
#define A_EJSL 24576
#define SC_P   180
#define A_SC   36096
#define ATT_P  92          // attn bf16 pairs: hi at [0,8832), lo at [A_SC, A_SC+8832)
#define AP_P   260         // A' (ce bf16) pitch; hi at 13056, lo at 21376
#define A_APH  13056
#define A_APL  21376
#define BS_P   36          // Mbig chunk stage pitch; hi at A_SC, lo at A_SC+4608
#define ATTN_FLOATS 53376
#define ATTN_SMEM_BYTES (ATTN_FLOATS * 4)   // 213504

// k_gates smem layout (unsigned units, pitch 68)
#define GA_PITCH 68
#define G_AH  0
#define G_AL  (G_AH + 64 * GA_PITCH)
#define G_BH  (G_AL + 64 * GA_PITCH)
#define G_BL  (G_BH + 128 * GA_PITCH)
#define G_DS  (G_BL + 128 * GA_PITCH)
#define G_SMEM_BYTES ((G_DS + 64 * 33) * 4)   // 112896

// ---------------- device scratch ----------------
__device__ float g_W2[HH * 640];
__device__ float g_bqk[512];
__device__ float g_hfold[(size_t)BB * NN * 640];
__device__ float g_sfold[TT * 640];
__device__ float g_agg[2][BB * NN * HH];
__device__ float g_aggWh[2][BB * NN * 4 * HH];   // PERMUTED cols: p = hh*4 + gate
__device__ float g_comb[(size_t)NROWS * HH];
__device__ float g_x1[(size_t)NROWS * HH];
__device__ float g_x2[(size_t)NROWS * HH];
__device__ unsigned g_lnx_hi[(size_t)NROWS * 64];
__device__ unsigned g_lnx_lo[(size_t)NROWS * 64];
__device__ __nv_bfloat16 g_WxT_hi[2][512 * 128];
__device__ __nv_bfloat16 g_WxT_lo[2][512 * 128];
__device__ float g_WoC[HH * HH];                 // Wo @ ctxW2
__device__ float g_cvec[HH];                     // ctxb + bo@ctxW2 + bv@WoC
__device__ unsigned g_MTp_hi[128 * 256];         // MbigT bf16 pairs [c][h*64+j2]
__device__ unsigned g_MTp_lo[128 * 256];

__device__ __forceinline__ float sigf(float x) {
    return __fdividef(1.f, 1.f + __expf(fminf(-x, 80.f)));
}
__device__ __forceinline__ float tanhfast(float x) {
    float e = __expf(fminf(2.f * x, 80.f));
    return __fdividef(e - 1.f, e + 1.f);
}
__device__ __forceinline__ unsigned pack_bf(float lo, float hi) {
    unsigned r;
    asm("cvt.rn.bf16x2.f32 %0, %1, %2;" : "=r"(r) : "f"(hi), "f"(lo));
    return r;
}
__device__ __forceinline__ void split2(float a, float b, unsigned& h, unsigned& l) {
    h = pack_bf(a, b);
    __nv_bfloat162 hb = *(__nv_bfloat162*)&h;
    l = pack_bf(a - __bfloat162float(hb.x), b - __bfloat162float(hb.y));
}
// HMMA m16n8k16 bf16 -> fp32 (family-portable)
__device__ __forceinline__ void mma16816(float* c, unsigned a0, unsigned a1,
                                         unsigned a2, unsigned a3,
                                         unsigned b0, unsigned b1) {
    asm volatile(
        "mma.sync.aligned.m16n8k16.row.col.f32.bf16.bf16.f32 "
        "{%0,%1,%2,%3}, {%4,%5,%6,%7}, {%8,%9}, {%0,%1,%2,%3};"
        : "+f"(c[0]), "+f"(c[1]), "+f"(c[2]), "+f"(c[3])
        : "r"(a0), "r"(a1), "r"(a2), "r"(a3), "r"(b0), "r"(b1));
}

// ---------------- prep kernels ----------------
__global__ void k_w2(const float* __restrict__ Wq, const float* __restrict__ Wk,
                     const float* __restrict__ ctxW, const float* __restrict__ bq) {
    int idx = blockIdx.x * 256 + threadIdx.x;
    int i = idx / 640, col = idx % 640;
    if (i < HH) {
        float acc;
        if (col < 512) {
            int h = col >> 7, j = col & 127;
            acc = 0.f;
            #pragma unroll 8
            for (int d = 0; d < 32; d++)
                acc += Wq[i * HH + h * 32 + d] * Wk[j * HH + h * 32 + d];
        } else {
            acc = ctxW[i * HH + (col - 512)];
        }
        g_W2[i * 640 + col] = acc;
    }
    if (idx < 512) {
        int h = idx >> 7, j = idx & 127;
        float a = 0.f;
        #pragma unroll 8
        for (int d = 0; d < 32; d++)
            a += bq[h * 32 + d] * Wk[j * HH + h * 32 + d];
        g_bqk[idx] = a;
    }
}

__global__ void k_wprep(const float* __restrict__ Wx0, const float* __restrict__ Wx1) {
    int idx = blockIdx.x * 256 + threadIdx.x;
    if (idx >= 2 * 512 * 128) return;
    int l = idx / (512 * 128);
    int rem = idx % (512 * 128);
    int p = rem / 128, i = rem % 128;
    const float* Wx = l ? Wx1 : Wx0;
    float v = Wx[i * 512 + (p & 3) * 128 + (p >> 2)];
    __nv_bfloat16 hi = __float2bfloat16(v);
    float lo = v - __bfloat162float(hi);
    g_WxT_hi[l][p * 128 + i] = hi;
    g_WxT_lo[l][p * 128 + i] = __float2bfloat16(lo);
}

// WoC = Wo @ ctxW2
__global__ void k_woc(const float* __restrict__ Wo, const float* __restrict__ ctxW) {
    int idx = blockIdx.x * 256 + threadIdx.x;   // 16384
    int i = idx >> 7, c = idx & 127;
    float acc = 0.f;
    #pragma unroll 4
    for (int m = 0; m < 128; m++)
        acc += Wo[i * 128 + m] * ctxW[(128 + m) * 128 + c];
    g_WoC[i * 128 + c] = acc;
}

// MbigT[c][h*64+j2] pairs: M_h[j][c] = sum_d Wv[j][h*32+d]*WoC[h*32+d][c]
__global__ void k_mbig(const float* __restrict__ Wv) {
    int idx = blockIdx.x * 256 + threadIdx.x;   // 32768
    int c = idx >> 8, pr = idx & 255;
    int h = pr >> 6, j2 = pr & 63;
    float m0 = 0.f, m1 = 0.f;
    #pragma unroll 8
    for (int d = 0; d < 32; d++) {
        float wc = g_WoC[(h * 32 + d) * 128 + c];
        m0 += Wv[(2 * j2) * 128 + h * 32 + d] * wc;
        m1 += Wv[(2 * j2 + 1) * 128 + h * 32 + d] * wc;
    }
    unsigned hh_, ll_;
    split2(m0, m1, hh_, ll_);
    g_MTp_hi[idx] = hh_;
    g_MTp_lo[idx] = ll_;
}

__global__ void k_cvec(const float* __restrict__ ctxb, const float* __restrict__ bo,
                       const float* __restrict__ bv, const float* __restrict__ ctxW) {
    int c = threadIdx.x;
    float acc = ctxb[c];
    #pragma unroll 4
    for (int i = 0; i < 128; i++) acc += bo[i] * ctxW[(128 + i) * 128 + c];
    #pragma unroll 4
    for (int j = 0; j < 128; j++) acc += bv[j] * g_WoC[j * 128 + c];
    g_cvec[c] = acc;
}

__global__ __launch_bounds__(640, 1)
void k_fold(const float* __restrict__ h1, const float* __restrict__ stepq) {
    __shared__ float aS[8 * HH];
    int r0 = blockIdx.x * 8;
    bool isq = (r0 >= BB * NN);
    const float* src = isq ? (stepq + (r0 - BB * NN) * HH) : (h1 + (size_t)r0 * HH);
    for (int idx = threadIdx.x; idx < 8 * HH; idx += 640) aS[idx] = src[idx];
    __syncthreads();
    int c = threadIdx.x;
    float acc[8];
    float binit = (isq && c < 512) ? g_bqk[c] : 0.f;
    #pragma unroll
    for (int k = 0; k < 8; k++) acc[k] = binit;
    #pragma unroll 4
    for (int i = 0; i < HH; i++) {
        float w = g_W2[i * 640 + c];
        #pragma unroll
        for (int k = 0; k < 8; k++) acc[k] += aS[k * HH + i] * w;
    }
    float* dst = isq ? (g_sfold + (r0 - BB * NN) * 640) : (g_hfold + (size_t)r0 * 640);
    #pragma unroll
    for (int k = 0; k < 8; k++) dst[k * 640 + c] = acc[k];
}

__global__ __launch_bounds__(512, 1)
void k_agg(const float* __restrict__ h0, const float* __restrict__ h1,
           const float* __restrict__ adj) {
    extern __shared__ float hS[];
    int c5 = blockIdx.x / 32;
    int lb = blockIdx.x % 32;
    int l = lb >> 4, b = lb & 15;
    const float* hsrc = (l ? h1 : h0) + (size_t)b * NN * HH;
    for (int idx = threadIdx.x; idx < NN * HH; idx += 512) hS[idx] = hsrc[idx];
    __syncthreads();
    int hh = threadIdx.x & 127, g = threadIdx.x >> 7;
    const float4* adj4 = (const float4*)adj;
    int n0 = g * 50 + c5 * 10;
    float acc[10];
    #pragma unroll
    for (int k = 0; k < 10; k++) acc[k] = 0.f;
    for (int m4 = 0; m4 < 50; m4++) {
        float4 av[10];
        #pragma unroll
        for (int k = 0; k < 10; k++) av[k] = adj4[(n0 + k) * 50 + m4];
        #pragma unroll
        for (int u = 0; u < 4; u++) {
            float hv = hS[(m4 * 4 + u) * HH + hh];
            #pragma unroll
            for (int k = 0; k < 10; k++)
                acc[k] += ((const float*)&av[k])[u] * hv;
        }
    }
    #pragma unroll
    for (int k = 0; k < 10; k++)
        g_agg[l][((size_t)b * NN + n0 + k) * HH + hh] = acc[k];
}

__global__ __launch_bounds__(512, 1)
void k_aggWh(const float* __restrict__ Wh0, const float* __restrict__ bb0,
             const float* __restrict__ Wh1, const float* __restrict__ bb1) {
    extern __shared__ float aggS[];
    int ch = blockIdx.x >> 5;
    int lb = blockIdx.x & 31;
    int l = lb >> 4, b = lb & 15;
    const float* Wh   = l ? Wh1 : Wh0;
    const float* bias = l ? bb1 : bb0;
    const float* asrc = g_agg[l] + (size_t)b * NN * HH;
    for (int idx = threadIdx.x; idx < NN * HH; idx += 512) aggS[idx] = asrc[idx];
    __syncthreads();
    int c = threadIdx.x;
    int perm = (c & 127) * 4 + (c >> 7);
    float bsv = bias[c];
    const float4* a4 = (const float4*)aggS;
    float* dst = g_aggWh[l] + (size_t)b * NN * 4 * HH;
    int n0 = ch * 50;
    float acc[50];
    #pragma unroll
    for (int k = 0; k < 50; k++) acc[k] = bsv;
    for (int i4 = 0; i4 < 32; i4++) {
        float w0 = Wh[(i4 * 4 + 0) * 512 + c];
        float w1 = Wh[(i4 * 4 + 1) * 512 + c];
        float w2 = Wh[(i4 * 4 + 2) * 512 + c];
        float w3 = Wh[(i4 * 4 + 3) * 512 + c];
        #pragma unroll
        for (int k = 0; k < 50; k++) {
            float4 a = a4[(n0 + k) * 32 + i4];
            acc[k] += a.x * w0 + a.y * w1 + a.z * w2 + a.w * w3;
        }
    }
    #pragma unroll
    for (int k = 0; k < 50; k++) dst[(n0 + k) * 512 + perm] = acc[k];
}

// ---------------- attention megakernel v3 ----------------
__global__ __launch_bounds__(512, 1)
void k_attn(const float* __restrict__ enc, float* __restrict__ out_attn)
{
    extern __shared__ float sm[];
    unsigned* su = (unsigned*)sm;
    float* sc = sm + A_SC;

    const int tid = threadIdx.x;
    const int b = blockIdx.x / NN, n = blockIdx.x % NN;
    const int bn = b * NN + n;
    const int w = tid >> 5, lane = tid & 31;
    const int g = lane >> 2, tg = lane & 3;

    // ---- P0: e_sj bf16 h/l + qt bf16 h/l ----
    {
        const float4* e4 = (const float4*)enc;
        for (int idx = tid; idx < SS * 32; idx += 512) {
            int s = idx >> 5, j4 = idx & 31;
            float4 v = e4[((size_t)(b * SS + s) * NN + n) * 32 + j4];
            unsigned h0, l0, h1, l1;
            split2(v.x, v.y, h0, l0);
            split2(v.z, v.w, h1, l1);
            unsigned* dh = su + A_ESJH + s * QT_P + j4 * 2;
            unsigned* dl = su + A_ESJL + s * QT_P + j4 * 2;
            dh[0] = h0; dh[1] = h1;
            dl[0] = l0; dl[1] = l1;
        }
        const float4* sf4 = (const float4*)g_sfold;
        const float4* hf4 = (const float4*)(g_hfold + (size_t)bn * 640);
        for (int idx = tid; idx < 96 * 32; idx += 512) {
            int r = idx >> 5, j4 = idx & 31;
            int t = r >> 2;
            float4 sa = sf4[t * 160 + (r & 3) * 32 + j4];
            float4 hb = hf4[(r & 3) * 32 + j4];
            unsigned h0, l0, h1, l1;
            split2(sa.x + hb.x, sa.y + hb.y, h0, l0);
            split2(sa.z + hb.z, sa.w + hb.w, h1, l1);
            unsigned* dh = su + A_QTH + r * QT_P + j4 * 2;
            unsigned* dl = su + A_QTL + r * QT_P + j4 * 2;
            dh[0] = h0; dh[1] = h1;
            dl[0] = l0; dl[1] = l1;
        }
    }
    __syncthreads();

    // ---- P3: scores = qt @ e^T (HMMA) -> sc fp32 ----
    {
        const float scale = 0.17677669529663687f;
        for (int job = w; job < 126; job += 16) {
            int mt = job / 21, nt = job % 21;
            float acc[4] = {0.f, 0.f, 0.f, 0.f};
            int ra = (mt * 16 + g) * QT_P;
            int rb = (nt * 8 + g) * QT_P;
            #pragma unroll
            for (int kt = 0; kt < 8; kt++) {
                int ko = kt * 8 + tg;
                unsigned a0h = su[A_QTH + ra + ko];
                unsigned a1h = su[A_QTH + ra + 8 * QT_P + ko];
                unsigned a2h = su[A_QTH + ra + ko + 4];
                unsigned a3h = su[A_QTH + ra + 8 * QT_P + ko + 4];
                unsigned a0l = su[A_QTL + ra + ko];
                unsigned a1l = su[A_QTL + ra + 8 * QT_P + ko];
                unsigned a2l = su[A_QTL + ra + ko + 4];
                unsigned a3l = su[A_QTL + ra + 8 * QT_P + ko + 4];
                unsigned b0h = su[A_ESJH + rb + ko];
                unsigned b1h = su[A_ESJH + rb + ko + 4];
                unsigned b0l = su[A_ESJL + rb + ko];
                unsigned b1l = su[A_ESJL + rb + ko + 4];
                mma16816(acc, a0h, a1h, a2h, a3h, b0h, b1h);
                mma16816(acc, a0h, a1h, a2h, a3h, b0l, b1l);
                mma16816(acc, a0l, a1l, a2l, a3l, b0h, b1h);
            }
            int row = mt * 16 + g, col = nt * 8 + 2 * tg;
            *(float2*)&sc[row * SC_P + col]       = make_float2(acc[0] * scale, acc[1] * scale);
            *(float2*)&sc[(row + 8) * SC_P + col] = make_float2(acc[2] * scale, acc[3] * scale);
        }
    }
    __syncthreads();

    // ---- load e_js bf16 h/l (overwrites e_sj region; qt region now dead) ----
    {
        const float* eb = enc + ((size_t)b * SS * NN + n) * HH;
        for (int idx = tid; idx < 128 * EJ_P; idx += 512) {
            int j = idx & 127, sp = idx >> 7;
            unsigned h, l;
            if (sp < 84) {
                float v0 = eb[(size_t)(2 * sp) * NN * HH + j];
                float v1 = eb[(size_t)(2 * sp + 1) * NN * HH + j];
                split2(v0, v1, h, l);
            } else { h = 0u; l = 0u; }
            su[A_EJSH + j * EJ_P + sp] = h;
            su[A_EJSL + j * EJ_P + sp] = l;
        }
    }

    // ---- P4: softmax (fp32 exact) -> global attn + smem bf16 pairs ----
    // hi -> su[0 + r*ATT_P + p] (dead qt region), lo -> su[A_SC + r*ATT_P + p]
    // lo writes only clobber fp32 score rows already read (stagger-safe).
    for (int k6 = 0; k6 < 6; k6++) {
        int r = k6 * 16 + w;
        float v[6];
        float mx = -1e30f;
        #pragma unroll
        for (int u = 0; u < 6; u++) {
            int s = lane + 32 * u;
            v[u] = (s < SS) ? sc[r * SC_P + s] : -1e30f;
            mx = fmaxf(mx, v[u]);
        }
        #pragma unroll
        for (int off = 16; off > 0; off >>= 1)
            mx = fmaxf(mx, __shfl_xor_sync(0xffffffffu, mx, off));
        float sum = 0.f;
        #pragma unroll
        for (int u = 0; u < 6; u++) {
            int s = lane + 32 * u;
            if (s < SS) { v[u] = __expf(v[u] - mx); sum += v[u]; }
        }
        #pragma unroll
        for (int off = 16; off > 0; off >>= 1)
            sum += __shfl_xor_sync(0xffffffffu, sum, off);
        float inv = __fdividef(1.f, sum);
        int t = r >> 2, h = r & 3;
        float* gout = out_attn + ((((size_t)b * TT + t) * NHH + h) * NN + n) * SS;
        #pragma unroll
        for (int u = 0; u < 6; u++) {
            int s = lane + 32 * u;
            if (s < SS) { v[u] *= inv; gout[s] = v[u]; }
            else v[u] = 0.f;
        }
        __syncthreads();   // all warps done reading this row-group's fp32 scores
        #pragma unroll
        for (int u = 0; u < 6; u++) {
            float av = v[u];
            float bnx = __shfl_down_sync(0xffffffffu, av, 1);
            int s = lane + 32 * u;
            if (!(lane & 1)) {
                int p = s >> 1;
                if (p < 88) {
                    unsigned hh_, ll_;
                    split2(av, bnx, hh_, ll_);
                    su[r * ATT_P + p] = hh_;
                    su[A_SC + r * ATT_P + p] = ll_;
                }
            }
        }
    }
    __syncthreads();

    // ---- P5: ce = attn @ e (HMMA); accumulators retained in registers ----
    float acc5[6][4];
    #pragma unroll
    for (int jj = 0; jj < 6; jj++)
        #pragma unroll
        for (int m = 0; m < 4; m++) acc5[jj][m] = 0.f;
    {
        int rb = (w * 8 + g) * EJ_P;   // nt = w
        #pragma unroll
        for (int jj = 0; jj < 6; jj++) {
            int ra = (jj * 16 + g) * ATT_P;
            #pragma unroll
            for (int kt = 0; kt < 11; kt++) {
                int ko = kt * 8 + tg;
                unsigned a0h = su[ra + ko];
                unsigned a1h = su[ra + 8 * ATT_P + ko];
                unsigned a2h = su[ra + ko + 4];
                unsigned a3h = su[ra + 8 * ATT_P + ko + 4];
                unsigned a0l = su[A_SC + ra + ko];
                unsigned a1l = su[A_SC + ra + 8 * ATT_P + ko];
                unsigned a2l = su[A_SC + ra + ko + 4];
                unsigned a3l = su[A_SC + ra + 8 * ATT_P + ko + 4];
                unsigned b0h = su[A_EJSH + rb + ko];
                unsigned b1h = su[A_EJSH + rb + ko + 4];
                unsigned b0l = su[A_EJSL + rb + ko];
                unsigned b1l = su[A_EJSL + rb + ko + 4];
                mma16816(acc5[jj], a0h, a1h, a2h, a3h, b0h, b1h);
                mma16816(acc5[jj], a0h, a1h, a2h, a3h, b0l, b1l);
                mma16816(acc5[jj], a0l, a1l, a2l, a3l, b0h, b1h);
            }
        }
    }
    __syncthreads();   // e_js fully consumed

    // ---- write A' = ce as bf16 [t][h*64+j2] pairs into dead e_js region ----
    {
        int j2 = w * 4 + tg;
        #pragma unroll
        for (int jj = 0; jj < 6; jj++) {
            int r0 = jj * 16 + g, r1 = r0 + 8;
            unsigned hh_, ll_;
            int p0 = (r0 & 3) * 64 + j2, t0 = r0 >> 2;
            split2(acc5[jj][0], acc5[jj][1], hh_, ll_);
            su[A_APH + t0 * AP_P + p0] = hh_;
            su[A_APL + t0 * AP_P + p0] = ll_;
            int p1 = (r1 & 3) * 64 + j2, t1 = r1 >> 2;
            split2(acc5[jj][2], acc5[jj][3], hh_, ll_);
            su[A_APH + t1 * AP_P + p1] = hh_;
            su[A_APL + t1 * AP_P + p1] = ll_;
        }
        for (int i = tid; i < 8 * 256; i += 512) {   // zero pad rows 24..31
            int rr = 24 + (i >> 8), p = i & 255;
            su[A_APH + rr * AP_P + p] = 0u;
            su[A_APL + rr * AP_P + p] = 0u;
        }
    }

    // ---- P6: comb = ce @ Mbig + folds + cvec (HMMA, 8 K-chunks) ----
    float acc6[2][4];
    #pragma unroll
    for (int mt = 0; mt < 2; mt++)
        #pragma unroll
        for (int m = 0; m < 4; m++) acc6[mt][m] = 0.f;

    for (int ck = 0; ck < 8; ck++) {
        __syncthreads();   // A' writes visible / prev chunk consumed (attn-lo dead)
        for (int i = tid; i < 4096; i += 512) {
            int c = i >> 5, pr = i & 31;
            su[A_SC + c * BS_P + pr]        = g_MTp_hi[c * 256 + ck * 32 + pr];
            su[A_SC + 4608 + c * BS_P + pr] = g_MTp_lo[c * 256 + ck * 32 + pr];
        }
        __syncthreads();
        int rb = (w * 8 + g) * BS_P;
        #pragma unroll
        for (int mt = 0; mt < 2; mt++) {
            int ra = (mt * 16 + g) * AP_P + ck * 32;
            #pragma unroll
            for (int kt = 0; kt < 4; kt++) {
                int ko = kt * 8 + tg;
                unsigned a0h = su[A_APH + ra + ko];
                unsigned a1h = su[A_APH + ra + 8 * AP_P + ko];
                unsigned a2h = su[A_APH + ra + ko + 4];
                unsigned a3h = su[A_APH + ra + 8 * AP_P + ko + 4];
                unsigned a0l = su[A_APL + ra + ko];
                unsigned a1l = su[A_APL + ra + 8 * AP_P + ko];
                unsigned a2l = su[A_APL + ra + ko + 4];
                unsigned a3l = su[A_APL + ra + 8 * AP_P + ko + 4];
                unsigned b0h = su[A_SC + rb + ko];
                unsigned b1h = su[A_SC + rb + ko + 4];
                unsigned b0l = su[A_SC + 4608 + rb + ko];
                unsigned b1l = su[A_SC + 4608 + rb + ko + 4];
                mma16816(acc6[mt], a0h, a1h, a2h, a3h, b0h, b1h);
                mma16816(acc6[mt], a0h, a1h, a2h, a3h, b0l, b1l);
                mma16816(acc6[mt], a0l, a1l, a2l, a3l, b0h, b1h);
            }
        }
    }
    // write comb rows 0..23
    {
        int c0 = w * 8 + 2 * tg;
        float2 cv = *(const float2*)&g_cvec[c0];
        float2 hf = *(const float2*)&g_hfold[(size_t)bn * 640 + 512 + c0];
        #pragma unroll
        for (int mt = 0; mt < 2; mt++) {
            int t0 = mt * 16 + g;
            float2 sf0 = *(const float2*)&g_sfold[t0 * 640 + 512 + c0];
            *(float2*)&g_comb[((size_t)bn * TT + t0) * HH + c0] =
                make_float2(acc6[mt][0] + cv.x + hf.x + sf0.x,
                            acc6[mt][1] + cv.y + hf.y + sf0.y);
            int t1 = t0 + 8;
            if (t1 < TT) {
                float2 sf1 = *(const float2*)&g_sfold[t1 * 640 + 512 + c0];
                *(float2*)&g_comb[((size_t)bn * TT + t1) * HH + c0] =
                    make_float2(acc6[mt][2] + cv.x + hf.x + sf1.x,
                                acc6[mt][3] + cv.y + hf.y + sf1.y);
            }
        }
    }
}

// ---------------- LN -> bf16 hi/lo ----------------
__global__ __launch_bounds__(512, 1)
void k_ln(int which, const float* __restrict__ lg, const float* __restrict__ lb) {
    const float* src = which ? g_x1 : g_comb;
    int warp = threadIdx.x >> 5, lane = threadIdx.x & 31;
    int row0 = blockIdx.x * 128;
    for (int it = 0; it < 8; it++) {
        int row = row0 + warp + it * 16;
        float4 x = ((const float4*)(src + (size_t)row * HH))[lane];
        float s1 = x.x + x.y + x.z + x.w;
        #pragma unroll
        for (int off = 16; off > 0; off >>= 1) s1 += __shfl_xor_sync(0xffffffffu, s1, off);
        float mean = s1 * (1.f / HH);
        float dx = x.x - mean, dy = x.y - mean, dz = x.z - mean, dw = x.w - mean;
        float s2 = dx * dx + dy * dy + dz * dz + dw * dw;
        #pragma unroll
        for (int off = 16; off > 0; off >>= 1) s2 += __shfl_xor_sync(0xffffffffu, s2, off);
        float inv = rsqrtf(s2 * (1.f / HH) + 1e-5f);
        float4 gg = ((const float4*)lg)[lane];
        float4 bbv = ((const float4*)lb)[lane];
        float y0 = dx * inv * gg.x + bbv.x;
        float y1 = dy * inv * gg.y + bbv.y;
        float y2 = dz * inv * gg.z + bbv.z;
        float y3 = dw * inv * gg.w + bbv.w;
        size_t o = (size_t)row * 64 + lane * 2;
        unsigned h0, l0, h1, l1;
        split2(y0, y1, h0, l0);
        split2(y2, y3, h1, l1);
        g_lnx_hi[o] = h0; g_lnx_hi[o + 1] = h1;
        g_lnx_lo[o] = l0; g_lnx_lo[o + 1] = l1;
    }
}

// ---------------- HMMA gates GEMM + fused LSTM cell ----------------
__global__ __launch_bounds__(256, 2)
void k_gates(int layer, const float* __restrict__ cg) {
    extern __shared__ unsigned su[];
    unsigned* Ah = su + G_AH;
    unsigned* Al = su + G_AL;
    unsigned* Bh = su + G_BH;
    unsigned* Bl = su + G_BL;
    float*    Ds = (float*)(su + G_DS);

    const float* resid = layer ? g_x1 : nullptr;
    float* xout = layer ? g_x2 : g_x1;

    const int tid = threadIdx.x;
    const int row0 = blockIdx.x * 64;
    const int w = tid >> 5, lane = tid & 31;
    const int g = lane >> 2, tg = lane & 3;
    const int mt = w >> 1, nh = w & 1;
    const int qpar = tg & 1;

    {
        const uint4* ah4 = (const uint4*)g_lnx_hi + (size_t)row0 * 16;
        const uint4* al4 = (const uint4*)g_lnx_lo + (size_t)row0 * 16;
        for (int i = tid; i < 64 * 16; i += 256) {
            int r = i >> 4, m = i & 15;
            *(uint4*)(Ah + r * GA_PITCH + m * 4) = ah4[r * 16 + m];
            *(uint4*)(Al + r * GA_PITCH + m * 4) = al4[r * 16 + m];
        }
    }
    const uint4* WH = (const uint4*)g_WxT_hi[layer];
    const uint4* WL = (const uint4*)g_WxT_lo[layer];

    for (int nc = 0; nc < 4; nc++) {
        __syncthreads();
        for (int i = tid; i < 128 * 16; i += 256) {
            int r = i >> 4, m = i & 15;
            *(uint4*)(Bh + r * GA_PITCH + m * 4) = WH[(nc * 128 + r) * 16 + m];
            *(uint4*)(Bl + r * GA_PITCH + m * 4) = WL[(nc * 128 + r) * 16 + m];
        }
        __syncthreads();

        float acc[8][4];
        #pragma unroll
        for (int q = 0; q < 8; q++)
            #pragma unroll
            for (int m = 0; m < 4; m++) acc[q][m] = 0.f;

        const int arow = mt * 16 + g;
        #pragma unroll
        for (int kt = 0; kt < 8; kt++) {
            const int ko = kt * 8 + tg;
            unsigned a0h = Ah[arow * GA_PITCH + ko];
            unsigned a1h = Ah[(arow + 8) * GA_PITCH + ko];
            unsigned a2h = Ah[arow * GA_PITCH + ko + 4];
            unsigned a3h = Ah[(arow + 8) * GA_PITCH + ko + 4];
            unsigned a0l = Al[arow * GA_PITCH + ko];
            unsigned a1l = Al[(arow + 8) * GA_PITCH + ko];
            unsigned a2l = Al[arow * GA_PITCH + ko + 4];
            unsigned a3l = Al[(arow + 8) * GA_PITCH + ko + 4];
            #pragma unroll
            for (int q = 0; q < 8; q++) {
                const int nrow = (nh * 8 + q) * 8 + g;
                unsigned b0h = Bh[nrow * GA_PITCH + ko];
                unsigned b1h = Bh[nrow * GA_PITCH + ko + 4];
                unsigned b0l = Bl[nrow * GA_PITCH + ko];
                unsigned b1l = Bl[nrow * GA_PITCH + ko + 4];
                mma16816(acc[q], a0h, a1h, a2h, a3h, b0h, b1h);
                mma16816(acc[q], a0h, a1h, a2h, a3h, b0l, b1l);
                mma16816(acc[q], a0l, a1l, a2l, a3l, b0h, b1h);
            }
        }

        #pragma unroll
        for (int q = 0; q < 8; q++) {
            float c0 = acc[q][0], c1 = acc[q][1], c2 = acc[q][2], c3 = acc[q][3];
            float r0 = __shfl_xor_sync(0xffffffffu, c0, 1);
            float r1 = __shfl_xor_sync(0xffffffffu, c1, 1);
            float r2 = __shfl_xor_sync(0xffffffffu, c2, 1);
            float r3 = __shfl_xor_sync(0xffffffffu, c3, 1);
            float gi = qpar ? r2 : c0;
            float gf = qpar ? r3 : c1;
            float gv = qpar ? c2 : r0;
            float go = qpar ? c3 : r1;
            int myrow = mt * 16 + g + 8 * qpar;
            int hhl = (nh * 8 + q) * 2 + (tg >> 1);
            int hh = nc * 32 + hhl;
            int grow = row0 + myrow;
            int bn = grow / TT;
            const float4 ag = *(const float4*)(g_aggWh[layer] + (size_t)bn * 512 + hh * 4);
            gi += ag.x; gf += ag.y; gv += ag.z; go += ag.w;
            float cv = cg[(size_t)bn * HH + hh];
            float cn = sigf(gf) * cv + sigf(gi) * tanhfast(gv);
            float hv = sigf(go) * tanhfast(cn);
            if (resid) hv += resid[(size_t)grow * HH + hh];
            Ds[myrow * 33 + hhl] = hv;
        }
        __syncthreads();

        for (int i = tid; i < 64 * 8; i += 256) {
            int r = i >> 3, m = i & 7;
            const float* d = Ds + r * 33 + m * 4;
            *(float4*)(xout + (size_t)(row0 + r) * HH + nc * 32 + m * 4) =
                make_float4(d[0], d[1], d[2], d[3]);
        }
    }
}

// ---------------- preds ----------------
__global__ __launch_bounds__(512, 1)
void k_preds(const float* __restrict__ outW, const float* __restrict__ outb,
             float* __restrict__ out_pred) {
    int warp = threadIdx.x >> 5, lane = threadIdx.x & 31;
    int row0 = blockIdx.x * 512;
    float4 w = ((const float4*)outW)[lane];
    float ob0 = outb[0];
    for (int it = 0; it < 32; it++) {
        int row = row0 + warp + it * 16;
        float4 x = ((const float4*)(g_x2 + (size_t)row * HH))[lane];
        float acc = x.x * w.x + x.y * w.y + x.z * w.z + x.w * w.w;
        #pragma unroll
        for (int off = 16; off > 0; off >>= 1)
            acc += __shfl_xor_sync(0xffffffffu, acc, off);
        if (lane == 0) {
            int bn = row / TT, t = row % TT;
            int b = bn / NN, n = bn % NN;
            out_pred[((size_t)b * TT + t) * NN + n] = acc + ob0;
        }
    }
}

extern "C" void kernel_launch(void* const* d_in, const int* in_sizes, int n_in,
                              void* d_out, int out_size) {
    const float* enc   = (const float*)d_in[0];
    const float* h0    = (const float*)d_in[1];
    const float* c0    = (const float*)d_in[2];
    const float* h1    = (const float*)d_in[3];
    const float* c1    = (const float*)d_in[4];
    const float* adj   = (const float*)d_in[5];
    const float* stepq = (const float*)d_in[6];
    const float* Wq    = (const float*)d_in[7];
    const float* bq    = (const float*)d_in[8];
    const float* Wk    = (const float*)d_in[9];
    // d_in[10] = bk: softmax-invariant, unused
    const float* Wv    = (const float*)d_in[11];
    const float* bv    = (const float*)d_in[12];
    const float* Wo    = (const float*)d_in[13];
    const float* bo    = (const float*)d_in[14];
    const float* ctxW  = (const float*)d_in[15];
    const float* ctxb  = (const float*)d_in[16];
    const float* Wx0   = (const float*)d_in[17];
    const float* Wh0   = (const float*)d_in[18];
    const float* b0    = (const float*)d_in[19];
    const float* lng0  = (const float*)d_in[20];
    const float* lnb0  = (const float*)d_in[21];
    const float* Wx1   = (const float*)d_in[22];
    const float* Wh1   = (const float*)d_in[23];
    const float* b1    = (const float*)d_in[24];
    const float* lng1  = (const float*)d_in[25];
    const float* lnb1  = (const float*)d_in[26];
    const float* outW  = (const float*)d_in[27];
    const float* outb  = (const float*)d_in[28];

    float* out      = (float*)d_out;
    float* out_pred = out;
    float* out_attn = out + (size_t)BB * TT * NN;

    cudaFuncSetAttribute(k_attn, cudaFuncAttributeMaxDynamicSharedMemorySize, ATTN_SMEM_BYTES);
    cudaFuncSetAttribute(k_agg, cudaFuncAttributeMaxDynamicSharedMemorySize, AGG_SMEM);
    cudaFuncSetAttribute(k_aggWh, cudaFuncAttributeMaxDynamicSharedMemorySize, AGG_SMEM);
    cudaFuncSetAttribute(k_gates, cudaFuncAttributeMaxDynamicSharedMemorySize, G_SMEM_BYTES);

    k_w2<<<320, 256>>>(Wq, Wk, ctxW, bq);
    k_wprep<<<512, 256>>>(Wx0, Wx1);
    k_woc<<<64, 256>>>(Wo, ctxW);
    k_mbig<<<128, 256>>>(Wv);
    k_cvec<<<1, 128>>>(ctxb, bo, bv, ctxW);
    k_fold<<<(BB * NN + TT) / 8, 640>>>(h1, stepq);
    k_agg<<<5 * 2 * BB, 512, AGG_SMEM>>>(h0, h1, adj);
    k_aggWh<<<4 * 2 * BB, 512, AGG_SMEM>>>(Wh0, b0, Wh1, b1);
    k_attn<<<BB * NN, 512, ATTN_SMEM_BYTES>>>(enc, out_attn);
    k_ln<<<NROWS / 128, 512>>>(0, lng0, lnb0);
    k_gates<<<NROWS / 64, 256, G_SMEM_BYTES>>>(0, c0);
    k_ln<<<NROWS / 128, 512>>>(1, lng1, lnb1);
    k_gates<<<NROWS / 64, 256, G_SMEM_BYTES>>>(1, c1);
    k_preds<<<NROWS / 512, 512>>>(outW, outb, out_pred);
}